// round 1
// baseline (speedup 1.0000x reference)
#include <cuda_runtime.h>

#define N_ 64
#define C_ 64
#define T_ 300
#define V_ 25
#define S_ 3
#define IC_ 16
#define OC_ 64
#define EPS_ 1e-5f

// kernel1 tiling: 25 chunks of 12 timesteps (exact: 25*12=300)
#define TT1 12
#define NC1 25
#define PTS1 (TT1 * V_)   // 300
#define P4_1 (PTS1 / 4)   // 75

// kernel3 tiling: 30 chunks of 10 timesteps
#define TT3 10
#define NC3 30
#define PTS3 (TT3 * V_)   // 250

// ---- device-global scratch (no allocations allowed) ----
__device__ float g_Mpart[N_ * NC1 * S_ * V_ * V_];   // [n][chunk][s*625+vw]  ~12MB
__device__ float g_Aadp[N_ * S_ * V_ * V_];          // [n][s][v][w]
__device__ float g_wdT[S_ * C_ * OC_];               // [s][c][o]

__device__ __forceinline__ float tanh_fast(float x) {
    float cx = fminf(fmaxf(x, -10.0f), 10.0f);
    float e = __expf(2.0f * cx);
    return __fdividef(e - 1.0f, e + 1.0f);
}

// =====================================================================
// Kernel 1: per (n, t-chunk): a,b = tanh(bn(conv)), partial M = a^T b
// =====================================================================
__global__ __launch_bounds__(256, 1)
void k1_mpart(const float* __restrict__ x,
              const float* __restrict__ wa, const float* __restrict__ ba,
              const float* __restrict__ wb, const float* __restrict__ bb,
              const float* __restrict__ gaA, const float* __restrict__ beA,
              const float* __restrict__ mA,  const float* __restrict__ vA,
              const float* __restrict__ gaB, const float* __restrict__ beB,
              const float* __restrict__ mB,  const float* __restrict__ vB)
{
    extern __shared__ float sm1[];
    float* xs   = sm1;             // 64*300 = 19200
    float* ab   = xs + 19200;      // 32*300 = 9600 (rows 0..15: a_i, 16..31: b_i)
    float* wab  = ab + 9600;       // 32*64 = 2048
    float* mulc = wab + 2048;      // 32
    float* addc = mulc + 32;       // 32
    float* Mloc = addc + 32;       // 3*625 = 1875

    const int n = blockIdx.y, chunk = blockIdx.x, tid = threadIdx.x;

    // load x tile (float4, layout xs[c][p], p = t_local*25+v)
    const float* xbase = x + (size_t)n * (C_ * T_ * V_) + chunk * PTS1;
    for (int idx = tid; idx < C_ * P4_1; idx += 256) {
        int c = idx / P4_1, q = idx % P4_1;
        float4 v = *(const float4*)(xbase + c * (T_ * V_) + q * 4);
        *(float4*)(xs + c * PTS1 + q * 4) = v;
    }
    for (int idx = tid; idx < S_ * V_ * V_; idx += 256) Mloc[idx] = 0.0f;
    __syncthreads();

    for (int s = 0; s < S_; ++s) {
        // stage weights + BN constants
        for (int idx = tid; idx < 2 * IC_ * C_; idx += 256) {
            int r = idx / C_, c = idx % C_;
            wab[idx] = (r < IC_) ? wa[(s * IC_ + r) * C_ + c]
                                 : wb[(s * IC_ + (r - IC_)) * C_ + c];
        }
        if (tid < 2 * IC_) {
            int r = tid;
            int i = (r < IC_) ? r : r - IC_;
            int off = s * IC_ + i;
            float g, be, mm, vv, bias;
            if (r < IC_) { g = gaA[off]; be = beA[off]; mm = mA[off]; vv = vA[off]; bias = ba[off]; }
            else         { g = gaB[off]; be = beB[off]; mm = mB[off]; vv = vB[off]; bias = bb[off]; }
            float sc = g * rsqrtf(vv + EPS_);
            mulc[r] = sc;
            addc[r] = be + (bias - mm) * sc;
        }
        __syncthreads();

        // stage1: compute a,b rows. tasks = (i-pair 0..7, p4 0..74)
        for (int task = tid; task < 8 * P4_1; task += 256) {
            int ip = task / P4_1;
            int q  = task % P4_1;
            int i0 = ip * 2, i1 = i0 + 1;
            float4 aa0 = {0,0,0,0}, aa1 = {0,0,0,0};
            float4 bb0 = {0,0,0,0}, bb1 = {0,0,0,0};
            const float* w0a = wab + i0 * C_;
            const float* w1a = wab + i1 * C_;
            const float* w0b = wab + (IC_ + i0) * C_;
            const float* w1b = wab + (IC_ + i1) * C_;
            #pragma unroll 8
            for (int c = 0; c < C_; ++c) {
                float4 xv = *(const float4*)(xs + c * PTS1 + q * 4);
                float wa0v = w0a[c], wa1v = w1a[c];
                float wb0v = w0b[c], wb1v = w1b[c];
                aa0.x = fmaf(wa0v, xv.x, aa0.x); aa0.y = fmaf(wa0v, xv.y, aa0.y);
                aa0.z = fmaf(wa0v, xv.z, aa0.z); aa0.w = fmaf(wa0v, xv.w, aa0.w);
                aa1.x = fmaf(wa1v, xv.x, aa1.x); aa1.y = fmaf(wa1v, xv.y, aa1.y);
                aa1.z = fmaf(wa1v, xv.z, aa1.z); aa1.w = fmaf(wa1v, xv.w, aa1.w);
                bb0.x = fmaf(wb0v, xv.x, bb0.x); bb0.y = fmaf(wb0v, xv.y, bb0.y);
                bb0.z = fmaf(wb0v, xv.z, bb0.z); bb0.w = fmaf(wb0v, xv.w, bb0.w);
                bb1.x = fmaf(wb1v, xv.x, bb1.x); bb1.y = fmaf(wb1v, xv.y, bb1.y);
                bb1.z = fmaf(wb1v, xv.z, bb1.z); bb1.w = fmaf(wb1v, xv.w, bb1.w);
            }
            float mu, ad;
            float4 r;
            mu = mulc[i0]; ad = addc[i0];
            r.x = tanh_fast(fmaf(aa0.x, mu, ad)); r.y = tanh_fast(fmaf(aa0.y, mu, ad));
            r.z = tanh_fast(fmaf(aa0.z, mu, ad)); r.w = tanh_fast(fmaf(aa0.w, mu, ad));
            *(float4*)(ab + i0 * PTS1 + q * 4) = r;
            mu = mulc[i1]; ad = addc[i1];
            r.x = tanh_fast(fmaf(aa1.x, mu, ad)); r.y = tanh_fast(fmaf(aa1.y, mu, ad));
            r.z = tanh_fast(fmaf(aa1.z, mu, ad)); r.w = tanh_fast(fmaf(aa1.w, mu, ad));
            *(float4*)(ab + i1 * PTS1 + q * 4) = r;
            mu = mulc[IC_ + i0]; ad = addc[IC_ + i0];
            r.x = tanh_fast(fmaf(bb0.x, mu, ad)); r.y = tanh_fast(fmaf(bb0.y, mu, ad));
            r.z = tanh_fast(fmaf(bb0.z, mu, ad)); r.w = tanh_fast(fmaf(bb0.w, mu, ad));
            *(float4*)(ab + (IC_ + i0) * PTS1 + q * 4) = r;
            mu = mulc[IC_ + i1]; ad = addc[IC_ + i1];
            r.x = tanh_fast(fmaf(bb1.x, mu, ad)); r.y = tanh_fast(fmaf(bb1.y, mu, ad));
            r.z = tanh_fast(fmaf(bb1.z, mu, ad)); r.w = tanh_fast(fmaf(bb1.w, mu, ad));
            *(float4*)(ab + (IC_ + i1) * PTS1 + q * 4) = r;
        }
        __syncthreads();

        // stage2: Mloc[s][v][w] += sum_{i,t} a[i][t,v]*b[i][t,w], 2x2 tiling
        if (tid < 169) {
            int vg = tid / 13, wg = tid % 13;
            int v0 = vg * 2, w0 = wg * 2;
            int v1c = min(v0 + 1, 24), w1c = min(w0 + 1, 24);
            float m00 = 0, m01 = 0, m10 = 0, m11 = 0;
            for (int i = 0; i < IC_; ++i) {
                const float* arow = ab + i * PTS1;
                const float* brow = ab + (IC_ + i) * PTS1;
                #pragma unroll
                for (int tl = 0; tl < TT1; ++tl) {
                    int base = tl * V_;
                    float a0 = arow[base + v0], a1 = arow[base + v1c];
                    float b0 = brow[base + w0], b1 = brow[base + w1c];
                    m00 = fmaf(a0, b0, m00); m01 = fmaf(a0, b1, m01);
                    m10 = fmaf(a1, b0, m10); m11 = fmaf(a1, b1, m11);
                }
            }
            float* Ms = Mloc + s * 625;
            Ms[v0 * 25 + w0] += m00;
            if (w0 + 1 < 25) Ms[v0 * 25 + w0 + 1] += m01;
            if (v0 + 1 < 25) Ms[(v0 + 1) * 25 + w0] += m10;
            if (w0 + 1 < 25 && v0 + 1 < 25) Ms[(v0 + 1) * 25 + w0 + 1] += m11;
        }
        __syncthreads();
    }

    float* dst = g_Mpart + (size_t)(n * NC1 + chunk) * (S_ * V_ * V_);
    for (int idx = tid; idx < S_ * V_ * V_; idx += 256) dst[idx] = Mloc[idx];
}

// =====================================================================
// Kernel 2: reduce partial M, A_adp = A + tanh(M/4800)*alpha; transpose Wd
// =====================================================================
__global__ void k2_aadp(const float* __restrict__ A, const float* __restrict__ alpha,
                        const float* __restrict__ wd)
{
    int gid = blockIdx.x * blockDim.x + threadIdx.x;
    if (gid < N_ * S_ * V_ * V_) {
        int n = gid / (S_ * V_ * V_);
        int r = gid % (S_ * V_ * V_);
        float sum = 0.0f;
        const float* src = g_Mpart + (size_t)n * NC1 * (S_ * V_ * V_) + r;
        #pragma unroll
        for (int ch = 0; ch < NC1; ++ch) sum += src[ch * (S_ * V_ * V_)];
        float Mval = sum * (1.0f / 4800.0f);
        g_Aadp[gid] = A[r] + tanh_fast(Mval) * alpha[0];
    }
    if (gid < S_ * C_ * OC_) {
        int s = gid / (C_ * OC_);
        int rem = gid % (C_ * OC_);
        int c = rem / OC_, o = rem % OC_;
        g_wdT[gid] = wd[(s * OC_ + o) * C_ + c];
    }
}

// =====================================================================
// Kernel 3: y = sum_s Wd[s]^T (x @ A_adp[s]) + BN + residual + relu
// One thread per (t,w) column; y[64] in registers.
// =====================================================================
__global__ __launch_bounds__(256, 1)
void k3_main(const float* __restrict__ x,
             const float* __restrict__ dbias,
             const float* __restrict__ bng, const float* __restrict__ bnb,
             const float* __restrict__ bnm, const float* __restrict__ bnv,
             float* __restrict__ out)
{
    extern __shared__ float sm3[];
    float* xs  = sm3;                      // 64*250 = 16000
    float* wds = xs + C_ * PTS3;           // 3*64*64 = 12288  ([s][c][o])
    float* as  = wds + S_ * C_ * OC_;      // 3*625 = 1875
    float* scs = as + S_ * V_ * V_;        // 64
    float* shs = scs + OC_;                // 64

    const int n = blockIdx.y, chunk = blockIdx.x, tid = threadIdx.x;
    const float* xbase = x + (size_t)n * (C_ * T_ * V_) + chunk * PTS3;
    for (int idx = tid; idx < C_ * (PTS3 / 2); idx += 256) {
        int c = idx / (PTS3 / 2), q = idx % (PTS3 / 2);
        float2 v = *(const float2*)(xbase + c * (T_ * V_) + q * 2);
        *(float2*)(xs + c * PTS3 + q * 2) = v;
    }
    for (int idx = tid; idx < S_ * C_ * OC_; idx += 256) wds[idx] = g_wdT[idx];
    const float* adp = g_Aadp + (size_t)n * (S_ * V_ * V_);
    for (int idx = tid; idx < S_ * V_ * V_; idx += 256) as[idx] = adp[idx];
    if (tid < OC_) {
        float scv = bng[tid] * rsqrtf(bnv[tid] + EPS_);
        float dbsum = dbias[tid] + dbias[OC_ + tid] + dbias[2 * OC_ + tid];
        scs[tid] = scv;
        shs[tid] = bnb[tid] + (dbsum - bnm[tid]) * scv;
    }
    __syncthreads();

    if (tid >= PTS3) return;
    const int tl = tid / V_, w = tid % V_;

    float y[OC_];
    #pragma unroll
    for (int o = 0; o < OC_; ++o) y[o] = 0.0f;

    for (int s = 0; s < S_; ++s) {
        float Ar[V_];
        #pragma unroll
        for (int v = 0; v < V_; ++v) Ar[v] = as[s * 625 + v * 25 + w];
        const float* wrow = wds + s * C_ * OC_;
        for (int c = 0; c < C_; ++c) {
            const float* xc = xs + c * PTS3 + tl * V_;
            float u0 = 0, u1 = 0, u2 = 0, u3 = 0;
            #pragma unroll
            for (int v = 0; v < 24; v += 4) {
                u0 = fmaf(xc[v],     Ar[v],     u0);
                u1 = fmaf(xc[v + 1], Ar[v + 1], u1);
                u2 = fmaf(xc[v + 2], Ar[v + 2], u2);
                u3 = fmaf(xc[v + 3], Ar[v + 3], u3);
            }
            u0 = fmaf(xc[24], Ar[24], u0);
            float u = (u0 + u1) + (u2 + u3);
            const float* wc = wrow + c * OC_;
            #pragma unroll
            for (int o4 = 0; o4 < OC_ / 4; ++o4) {
                float4 wv = *(const float4*)(wc + o4 * 4);
                y[o4 * 4 + 0] = fmaf(wv.x, u, y[o4 * 4 + 0]);
                y[o4 * 4 + 1] = fmaf(wv.y, u, y[o4 * 4 + 1]);
                y[o4 * 4 + 2] = fmaf(wv.z, u, y[o4 * 4 + 2]);
                y[o4 * 4 + 3] = fmaf(wv.w, u, y[o4 * 4 + 3]);
            }
        }
    }

    float* obase = out + (size_t)n * (C_ * T_ * V_) + chunk * PTS3 + tid;
    #pragma unroll
    for (int o = 0; o < OC_; ++o) {
        float val = fmaf(y[o], scs[o], shs[o]) + xs[o * PTS3 + tid];
        obase[o * (T_ * V_)] = fmaxf(val, 0.0f);
    }
}

// =====================================================================
extern "C" void kernel_launch(void* const* d_in, const int* in_sizes, int n_in,
                              void* d_out, int out_size)
{
    const float* x    = (const float*)d_in[0];
    const float* A    = (const float*)d_in[1];
    const float* alph = (const float*)d_in[2];
    const float* wa   = (const float*)d_in[3];
    const float* ba   = (const float*)d_in[4];
    const float* wb   = (const float*)d_in[5];
    const float* bb   = (const float*)d_in[6];
    const float* bag  = (const float*)d_in[7];
    const float* bab  = (const float*)d_in[8];
    const float* bam  = (const float*)d_in[9];
    const float* bav  = (const float*)d_in[10];
    const float* bbg  = (const float*)d_in[11];
    const float* bbb  = (const float*)d_in[12];
    const float* bbm  = (const float*)d_in[13];
    const float* bbv  = (const float*)d_in[14];
    const float* wd   = (const float*)d_in[15];
    const float* db   = (const float*)d_in[16];
    const float* bng  = (const float*)d_in[17];
    const float* bnbt = (const float*)d_in[18];
    const float* bnm  = (const float*)d_in[19];
    const float* bnv  = (const float*)d_in[20];
    float* out = (float*)d_out;

    const int SM1 = (19200 + 9600 + 2048 + 32 + 32 + 1875) * (int)sizeof(float); // ~131 KB
    const int SM3 = (16000 + 12288 + 1875 + 64 + 64) * (int)sizeof(float);       // ~121 KB
    cudaFuncSetAttribute(k1_mpart, cudaFuncAttributeMaxDynamicSharedMemorySize, SM1);
    cudaFuncSetAttribute(k3_main,  cudaFuncAttributeMaxDynamicSharedMemorySize, SM3);

    dim3 g1(NC1, N_);
    k1_mpart<<<g1, 256, SM1>>>(x, wa, ba, wb, bb, bag, bab, bam, bav, bbg, bbb, bbm, bbv);

    k2_aadp<<<(N_ * S_ * V_ * V_ + 255) / 256, 256>>>(A, alph, wd);

    dim3 g3(NC3, N_);
    k3_main<<<g3, 256, SM3>>>(x, db, bng, bnbt, bnm, bnv, out);
}

// round 2
// speedup vs baseline: 1.2241x; 1.2241x over previous
#include <cuda_runtime.h>

#define N_ 64
#define C_ 64
#define T_ 300
#define V_ 25
#define S_ 3
#define IC_ 16
#define OC_ 64
#define EPS_ 1e-5f

// kernel1 tiling: 75 chunks of 4 timesteps
#define TT1 4
#define NC1 75
#define PTS1 (TT1 * V_)   // 100
#define P4_1 (PTS1 / 4)   // 25

// kernel3 tiling: 30 chunks of 10 timesteps
#define TT3 10
#define NC3 30
#define PTS3 (TT3 * V_)   // 250
#define XP 28             // padded floats per (c, tl) row in k3 smem

// ---- device-global scratch (no allocations allowed) ----
__device__ float g_Mpart[N_ * NC1 * S_ * V_ * V_];   // 36MB
__device__ float g_Aadp[N_ * S_ * V_ * V_];
__device__ float g_wdT[S_ * C_ * OC_];               // [s][c][o]

__device__ __forceinline__ float tanh_fast(float x) {
    float cx = fminf(fmaxf(x, -10.0f), 10.0f);
    float e = __expf(2.0f * cx);
    return __fdividef(e - 1.0f, e + 1.0f);
}

// =====================================================================
// Kernel 1: per (n, 4-t chunk): a,b = tanh(bn(conv)) for ALL s, then
// partial M = a^T b written straight to gmem. 2 CTAs/SM.
// =====================================================================
__global__ __launch_bounds__(256, 2)
void k1_mpart(const float* __restrict__ x,
              const float* __restrict__ wa, const float* __restrict__ ba,
              const float* __restrict__ wb, const float* __restrict__ bb,
              const float* __restrict__ gaA, const float* __restrict__ beA,
              const float* __restrict__ mA,  const float* __restrict__ vA,
              const float* __restrict__ gaB, const float* __restrict__ beB,
              const float* __restrict__ mB,  const float* __restrict__ vB)
{
    extern __shared__ float sm1[];
    float* xs   = sm1;             // 64*100 = 6400
    float* ab   = xs + 6400;       // 3*32*100 = 9600 ([s][row][p], rows 0..15 a, 16..31 b)
    float* wab  = ab + 9600;       // 3*32*64 = 6144 ([s][row][c])
    float* mulc = wab + 6144;      // 96  ([s][row32])
    float* addc = mulc + 96;       // 96
    // total 22336 floats = 89344 B

    const int n = blockIdx.y, chunk = blockIdx.x, tid = threadIdx.x;

    // load x tile (float4): xs[c][p], p = t_local*25+v
    const float* xbase = x + (size_t)n * (C_ * T_ * V_) + chunk * PTS1;
    for (int idx = tid; idx < C_ * P4_1; idx += 256) {
        int c = idx / P4_1, q = idx % P4_1;
        float4 v = *(const float4*)(xbase + c * (T_ * V_) + q * 4);
        *(float4*)(xs + c * PTS1 + q * 4) = v;
    }
    // stage all weights: wab[s][r][c], r<16 -> wa row, r>=16 -> wb row
    for (int idx4 = tid; idx4 < (S_ * 32 * C_) / 4; idx4 += 256) {
        int s = idx4 / 512;
        int r = (idx4 / 16) % 32;
        int c4 = idx4 % 16;
        const float* src = (r < IC_) ? (wa + ((s * IC_ + r) * C_))
                                     : (wb + ((s * IC_ + (r - IC_)) * C_));
        *(float4*)(wab + (s * 32 + r) * C_ + c4 * 4) = *(const float4*)(src + c4 * 4);
    }
    if (tid < S_ * 32) {
        int s = tid / 32, r = tid % 32;
        int i = (r < IC_) ? r : r - IC_;
        int off = s * IC_ + i;
        float g, be, mm, vv, bias;
        if (r < IC_) { g = gaA[off]; be = beA[off]; mm = mA[off]; vv = vA[off]; bias = ba[off]; }
        else         { g = gaB[off]; be = beB[off]; mm = mB[off]; vv = vB[off]; bias = bb[off]; }
        float sc = g * rsqrtf(vv + EPS_);
        mulc[tid] = sc;
        addc[tid] = be + (bias - mm) * sc;
    }
    __syncthreads();

    // stage1: tasks = (s 0..2, i 0..15, q 0..24) = 1200. Each computes a_i, b_i
    // rows (4 p's each) for one s.
    for (int task = tid; task < S_ * IC_ * P4_1; task += 256) {
        int q = task % P4_1;
        int i = (task / P4_1) % IC_;
        int s = task / (IC_ * P4_1);
        const float* wra = wab + (s * 32 + i) * C_;
        const float* wrb = wab + (s * 32 + 16 + i) * C_;
        const float* xq  = xs + q * 4;
        float4 A = {0, 0, 0, 0};
        float4 B = {0, 0, 0, 0};
        #pragma unroll
        for (int c4 = 0; c4 < 16; ++c4) {
            float4 w4a = *(const float4*)(wra + c4 * 4);
            float4 w4b = *(const float4*)(wrb + c4 * 4);
            float4 x0 = *(const float4*)(xq + (c4 * 4 + 0) * PTS1);
            float4 x1 = *(const float4*)(xq + (c4 * 4 + 1) * PTS1);
            float4 x2 = *(const float4*)(xq + (c4 * 4 + 2) * PTS1);
            float4 x3 = *(const float4*)(xq + (c4 * 4 + 3) * PTS1);
            A.x = fmaf(w4a.x, x0.x, A.x); A.y = fmaf(w4a.x, x0.y, A.y);
            A.z = fmaf(w4a.x, x0.z, A.z); A.w = fmaf(w4a.x, x0.w, A.w);
            A.x = fmaf(w4a.y, x1.x, A.x); A.y = fmaf(w4a.y, x1.y, A.y);
            A.z = fmaf(w4a.y, x1.z, A.z); A.w = fmaf(w4a.y, x1.w, A.w);
            A.x = fmaf(w4a.z, x2.x, A.x); A.y = fmaf(w4a.z, x2.y, A.y);
            A.z = fmaf(w4a.z, x2.z, A.z); A.w = fmaf(w4a.z, x2.w, A.w);
            A.x = fmaf(w4a.w, x3.x, A.x); A.y = fmaf(w4a.w, x3.y, A.y);
            A.z = fmaf(w4a.w, x3.z, A.z); A.w = fmaf(w4a.w, x3.w, A.w);
            B.x = fmaf(w4b.x, x0.x, B.x); B.y = fmaf(w4b.x, x0.y, B.y);
            B.z = fmaf(w4b.x, x0.z, B.z); B.w = fmaf(w4b.x, x0.w, B.w);
            B.x = fmaf(w4b.y, x1.x, B.x); B.y = fmaf(w4b.y, x1.y, B.y);
            B.z = fmaf(w4b.y, x1.z, B.z); B.w = fmaf(w4b.y, x1.w, B.w);
            B.x = fmaf(w4b.z, x2.x, B.x); B.y = fmaf(w4b.z, x2.y, B.y);
            B.z = fmaf(w4b.z, x2.z, B.z); B.w = fmaf(w4b.z, x2.w, B.w);
            B.x = fmaf(w4b.w, x3.x, B.x); B.y = fmaf(w4b.w, x3.y, B.y);
            B.z = fmaf(w4b.w, x3.z, B.z); B.w = fmaf(w4b.w, x3.w, B.w);
        }
        float mu, ad;
        float4 r;
        mu = mulc[s * 32 + i]; ad = addc[s * 32 + i];
        r.x = tanh_fast(fmaf(A.x, mu, ad)); r.y = tanh_fast(fmaf(A.y, mu, ad));
        r.z = tanh_fast(fmaf(A.z, mu, ad)); r.w = tanh_fast(fmaf(A.w, mu, ad));
        *(float4*)(ab + (s * 32 + i) * PTS1 + q * 4) = r;
        mu = mulc[s * 32 + 16 + i]; ad = addc[s * 32 + 16 + i];
        r.x = tanh_fast(fmaf(B.x, mu, ad)); r.y = tanh_fast(fmaf(B.y, mu, ad));
        r.z = tanh_fast(fmaf(B.z, mu, ad)); r.w = tanh_fast(fmaf(B.w, mu, ad));
        *(float4*)(ab + (s * 32 + 16 + i) * PTS1 + q * 4) = r;
    }
    __syncthreads();

    // stage2: M[s][v][w] = sum_{i,t} a[s][i][t,v]*b[s][i][t,w], 2x2 tiling.
    // tasks = 3 * 169 = 507. Write straight to gmem (each element once).
    float* dst = g_Mpart + (size_t)(n * NC1 + chunk) * (S_ * V_ * V_);
    for (int task = tid; task < S_ * 169; task += 256) {
        int s = task / 169, r = task % 169;
        int vg = r / 13, wg = r % 13;
        int v0 = vg * 2, w0 = wg * 2;
        int v1c = min(v0 + 1, 24), w1c = min(w0 + 1, 24);
        float m00 = 0, m01 = 0, m10 = 0, m11 = 0;
        const float* abs_ = ab + s * 3200;
        for (int i = 0; i < IC_; ++i) {
            const float* arow = abs_ + i * PTS1;
            const float* brow = abs_ + (16 + i) * PTS1;
            #pragma unroll
            for (int tl = 0; tl < TT1; ++tl) {
                int base = tl * V_;
                float a0 = arow[base + v0], a1 = arow[base + v1c];
                float b0 = brow[base + w0], b1 = brow[base + w1c];
                m00 = fmaf(a0, b0, m00); m01 = fmaf(a0, b1, m01);
                m10 = fmaf(a1, b0, m10); m11 = fmaf(a1, b1, m11);
            }
        }
        float* Ms = dst + s * 625;
        Ms[v0 * 25 + w0] = m00;
        if (w0 + 1 < 25) Ms[v0 * 25 + w0 + 1] = m01;
        if (v0 + 1 < 25) Ms[(v0 + 1) * 25 + w0] = m10;
        if (w0 + 1 < 25 && v0 + 1 < 25) Ms[(v0 + 1) * 25 + w0 + 1] = m11;
    }
}

// =====================================================================
// Kernel 2: reduce partial M, A_adp = A + tanh(M/4800)*alpha; transpose Wd
// =====================================================================
__global__ void k2_aadp(const float* __restrict__ A, const float* __restrict__ alpha,
                        const float* __restrict__ wd)
{
    int gid = blockIdx.x * blockDim.x + threadIdx.x;
    if (gid < N_ * S_ * V_ * V_) {
        int n = gid / (S_ * V_ * V_);
        int r = gid % (S_ * V_ * V_);
        float sum = 0.0f;
        const float* src = g_Mpart + (size_t)n * NC1 * (S_ * V_ * V_) + r;
        #pragma unroll 5
        for (int ch = 0; ch < NC1; ++ch) sum += src[(size_t)ch * (S_ * V_ * V_)];
        float Mval = sum * (1.0f / 4800.0f);
        g_Aadp[gid] = A[r] + tanh_fast(Mval) * alpha[0];
    }
    if (gid < S_ * C_ * OC_) {
        int s = gid / (C_ * OC_);
        int rem = gid % (C_ * OC_);
        int c = rem / OC_, o = rem % OC_;
        g_wdT[gid] = wd[(s * OC_ + o) * C_ + c];
    }
}

// =====================================================================
// Kernel 3: y = sum_s Wd[s]^T (x @ A_adp[s]) + BN + residual + relu
// One thread per (t,w) column; y[64] in registers. Per-s weight staging
// keeps smem at ~91KB -> 2 CTAs/SM.
// =====================================================================
__global__ __launch_bounds__(256, 2)
void k3_main(const float* __restrict__ x,
             const float* __restrict__ dbias,
             const float* __restrict__ bng, const float* __restrict__ bnb,
             const float* __restrict__ bnm, const float* __restrict__ bnv,
             float* __restrict__ out)
{
    extern __shared__ float sm3[];
    float* xs  = sm3;                      // 64 * TT3 * XP = 17920 (padded)
    float* wds = xs + C_ * TT3 * XP;       // 64*64 = 4096  ([c][o]) one s at a time
    float* as  = wds + C_ * OC_;           // 625
    float* scs = as + V_ * V_;             // 64
    float* shs = scs + OC_;                // 64
    // total 22769 floats = 91076 B

    const int n = blockIdx.y, chunk = blockIdx.x, tid = threadIdx.x;
    const float* xbase = x + (size_t)n * (C_ * T_ * V_) + chunk * PTS3;

    // load x tile into padded layout xs[c][tl][v] (row pitch XP=28 -> 16B aligned)
    for (int idx = tid; idx < C_ * PTS3; idx += 256) {
        int c = idx / PTS3, p = idx % PTS3;
        int tl = p / V_, v = p % V_;
        xs[c * (TT3 * XP) + tl * XP + v] = xbase[c * (T_ * V_) + p];
    }
    if (tid < OC_) {
        float scv = bng[tid] * rsqrtf(bnv[tid] + EPS_);
        float dbsum = dbias[tid] + dbias[OC_ + tid] + dbias[2 * OC_ + tid];
        scs[tid] = scv;
        shs[tid] = bnb[tid] + (dbsum - bnm[tid]) * scv;
    }

    const int tl = tid / V_, w = tid % V_;
    const bool active = (tid < PTS3);

    float y[OC_];
    #pragma unroll
    for (int o = 0; o < OC_; ++o) y[o] = 0.0f;

    const float* adp = g_Aadp + (size_t)n * (S_ * V_ * V_);

    for (int s = 0; s < S_; ++s) {
        __syncthreads();   // previous-s consumers done (also covers initial loads)
        for (int idx4 = tid; idx4 < (C_ * OC_) / 4; idx4 += 256)
            *(float4*)(wds + idx4 * 4) = *(const float4*)(g_wdT + s * C_ * OC_ + idx4 * 4);
        for (int idx = tid; idx < V_ * V_; idx += 256)
            as[idx] = adp[s * V_ * V_ + idx];
        __syncthreads();

        if (active) {
            float Ar[V_];
            #pragma unroll
            for (int v = 0; v < V_; ++v) Ar[v] = as[v * V_ + w];
            #pragma unroll 2
            for (int c = 0; c < C_; ++c) {
                const float* xc = xs + c * (TT3 * XP) + tl * XP;
                // 25-dot, vectorized (xc is 16B-aligned)
                float4 xa = *(const float4*)(xc + 0);
                float4 xb = *(const float4*)(xc + 4);
                float4 xcv = *(const float4*)(xc + 8);
                float4 xd = *(const float4*)(xc + 12);
                float4 xe = *(const float4*)(xc + 16);
                float4 xf = *(const float4*)(xc + 20);
                float xg = xc[24];
                float u0 = xa.x * Ar[0], u1 = xa.y * Ar[1], u2 = xa.z * Ar[2], u3 = xa.w * Ar[3];
                u0 = fmaf(xb.x, Ar[4], u0); u1 = fmaf(xb.y, Ar[5], u1);
                u2 = fmaf(xb.z, Ar[6], u2); u3 = fmaf(xb.w, Ar[7], u3);
                u0 = fmaf(xcv.x, Ar[8], u0); u1 = fmaf(xcv.y, Ar[9], u1);
                u2 = fmaf(xcv.z, Ar[10], u2); u3 = fmaf(xcv.w, Ar[11], u3);
                u0 = fmaf(xd.x, Ar[12], u0); u1 = fmaf(xd.y, Ar[13], u1);
                u2 = fmaf(xd.z, Ar[14], u2); u3 = fmaf(xd.w, Ar[15], u3);
                u0 = fmaf(xe.x, Ar[16], u0); u1 = fmaf(xe.y, Ar[17], u1);
                u2 = fmaf(xe.z, Ar[18], u2); u3 = fmaf(xe.w, Ar[19], u3);
                u0 = fmaf(xf.x, Ar[20], u0); u1 = fmaf(xf.y, Ar[21], u1);
                u2 = fmaf(xf.z, Ar[22], u2); u3 = fmaf(xf.w, Ar[23], u3);
                u0 = fmaf(xg, Ar[24], u0);
                float u = (u0 + u1) + (u2 + u3);
                const float* wc = wds + c * OC_;
                #pragma unroll
                for (int o4 = 0; o4 < OC_ / 4; ++o4) {
                    float4 wv = *(const float4*)(wc + o4 * 4);
                    y[o4 * 4 + 0] = fmaf(wv.x, u, y[o4 * 4 + 0]);
                    y[o4 * 4 + 1] = fmaf(wv.y, u, y[o4 * 4 + 1]);
                    y[o4 * 4 + 2] = fmaf(wv.z, u, y[o4 * 4 + 2]);
                    y[o4 * 4 + 3] = fmaf(wv.w, u, y[o4 * 4 + 3]);
                }
            }
        }
    }

    if (active) {
        float* obase = out + (size_t)n * (C_ * T_ * V_) + chunk * PTS3 + tid;
        #pragma unroll
        for (int o = 0; o < OC_; ++o) {
            float val = fmaf(y[o], scs[o], shs[o]) + xs[o * (TT3 * XP) + tl * XP + w];
            obase[o * (T_ * V_)] = fmaxf(val, 0.0f);
        }
    }
}

// =====================================================================
extern "C" void kernel_launch(void* const* d_in, const int* in_sizes, int n_in,
                              void* d_out, int out_size)
{
    const float* x    = (const float*)d_in[0];
    const float* A    = (const float*)d_in[1];
    const float* alph = (const float*)d_in[2];
    const float* wa   = (const float*)d_in[3];
    const float* ba   = (const float*)d_in[4];
    const float* wb   = (const float*)d_in[5];
    const float* bb   = (const float*)d_in[6];
    const float* bag  = (const float*)d_in[7];
    const float* bab  = (const float*)d_in[8];
    const float* bam  = (const float*)d_in[9];
    const float* bav  = (const float*)d_in[10];
    const float* bbg  = (const float*)d_in[11];
    const float* bbb  = (const float*)d_in[12];
    const float* bbm  = (const float*)d_in[13];
    const float* bbv  = (const float*)d_in[14];
    const float* wd   = (const float*)d_in[15];
    const float* db   = (const float*)d_in[16];
    const float* bng  = (const float*)d_in[17];
    const float* bnbt = (const float*)d_in[18];
    const float* bnm  = (const float*)d_in[19];
    const float* bnv  = (const float*)d_in[20];
    float* out = (float*)d_out;

    const int SM1 = 22336 * (int)sizeof(float); // 89344 B
    const int SM3 = 22769 * (int)sizeof(float); // 91076 B
    cudaFuncSetAttribute(k1_mpart, cudaFuncAttributeMaxDynamicSharedMemorySize, SM1);
    cudaFuncSetAttribute(k3_main,  cudaFuncAttributeMaxDynamicSharedMemorySize, SM3);

    dim3 g1(NC1, N_);
    k1_mpart<<<g1, 256, SM1>>>(x, wa, ba, wb, bb, bag, bab, bam, bav, bbg, bbb, bbm, bbv);

    k2_aadp<<<(N_ * S_ * V_ * V_ + 255) / 256, 256>>>(A, alph, wd);

    dim3 g3(NC3, N_);
    k3_main<<<g3, 256, SM3>>>(x, db, bng, bnbt, bnm, bnv, out);
}

// round 3
// speedup vs baseline: 1.6619x; 1.3576x over previous
#include <cuda_runtime.h>
#include <cstdint>

#define N_ 64
#define C_ 64
#define T_ 300
#define V_ 25
#define S_ 3
#define IC_ 16
#define OC_ 64
#define EPS_ 1e-5f

// kernel1 tiling: 75 chunks of 4 timesteps
#define TT1 4
#define NC1 75
#define PTS1 (TT1 * V_)   // 100
#define P4_1 (PTS1 / 4)   // 25

// kernel3 tiling: 60 chunks of 5 timesteps
#define TT3 5
#define NC3 60
#define NN3 (TT3 * V_)    // 125 output columns per chunk
#define XSP 140           // xs pitch per c: 5*28
#define USP 136           // us pitch (128+8 -> bank-conflict-free frags)
#define WDP 72            // wds pitch (64+8)

// ---- device-global scratch (no allocations allowed) ----
__device__ float g_Mpart[N_ * NC1 * S_ * V_ * V_];   // 36MB
__device__ float g_Aadp[N_ * S_ * V_ * V_];
__device__ float g_wdT[S_ * C_ * OC_];               // [s][c][o], tf32-rounded

__device__ __forceinline__ float tanh_fast(float x) {
    float cx = fminf(fmaxf(x, -10.0f), 10.0f);
    float e = __expf(2.0f * cx);
    return __fdividef(e - 1.0f, e + 1.0f);
}

__device__ __forceinline__ float to_tf32(float x) {
    uint32_t u;
    asm("cvt.rna.tf32.f32 %0, %1;" : "=r"(u) : "f"(x));
    return __uint_as_float(u);
}

__device__ __forceinline__ void mma_tf32(float c[4],
                                         uint32_t a0, uint32_t a1, uint32_t a2, uint32_t a3,
                                         uint32_t b0, uint32_t b1) {
    asm volatile("mma.sync.aligned.m16n8k8.row.col.f32.tf32.tf32.f32 "
                 "{%0,%1,%2,%3}, {%4,%5,%6,%7}, {%8,%9}, {%0,%1,%2,%3};"
                 : "+f"(c[0]), "+f"(c[1]), "+f"(c[2]), "+f"(c[3])
                 : "r"(a0), "r"(a1), "r"(a2), "r"(a3), "r"(b0), "r"(b1));
}

// =====================================================================
// Kernel 1: per (n, 4-t chunk): a,b = tanh(bn(conv)) for ALL s, then
// partial M = a^T b written straight to gmem. (unchanged from R2)
// =====================================================================
__global__ __launch_bounds__(256, 2)
void k1_mpart(const float* __restrict__ x,
              const float* __restrict__ wa, const float* __restrict__ ba,
              const float* __restrict__ wb, const float* __restrict__ bb,
              const float* __restrict__ gaA, const float* __restrict__ beA,
              const float* __restrict__ mA,  const float* __restrict__ vA,
              const float* __restrict__ gaB, const float* __restrict__ beB,
              const float* __restrict__ mB,  const float* __restrict__ vB)
{
    extern __shared__ float sm1[];
    float* xs   = sm1;             // 64*100
    float* ab   = xs + 6400;       // 3*32*100
    float* wab  = ab + 9600;       // 3*32*64
    float* mulc = wab + 6144;      // 96
    float* addc = mulc + 96;       // 96

    const int n = blockIdx.y, chunk = blockIdx.x, tid = threadIdx.x;

    const float* xbase = x + (size_t)n * (C_ * T_ * V_) + chunk * PTS1;
    for (int idx = tid; idx < C_ * P4_1; idx += 256) {
        int c = idx / P4_1, q = idx % P4_1;
        float4 v = *(const float4*)(xbase + c * (T_ * V_) + q * 4);
        *(float4*)(xs + c * PTS1 + q * 4) = v;
    }
    for (int idx4 = tid; idx4 < (S_ * 32 * C_) / 4; idx4 += 256) {
        int s = idx4 / 512;
        int r = (idx4 / 16) % 32;
        int c4 = idx4 % 16;
        const float* src = (r < IC_) ? (wa + ((s * IC_ + r) * C_))
                                     : (wb + ((s * IC_ + (r - IC_)) * C_));
        *(float4*)(wab + (s * 32 + r) * C_ + c4 * 4) = *(const float4*)(src + c4 * 4);
    }
    if (tid < S_ * 32) {
        int s = tid / 32, r = tid % 32;
        int i = (r < IC_) ? r : r - IC_;
        int off = s * IC_ + i;
        float g, be, mm, vv, bias;
        if (r < IC_) { g = gaA[off]; be = beA[off]; mm = mA[off]; vv = vA[off]; bias = ba[off]; }
        else         { g = gaB[off]; be = beB[off]; mm = mB[off]; vv = vB[off]; bias = bb[off]; }
        float sc = g * rsqrtf(vv + EPS_);
        mulc[tid] = sc;
        addc[tid] = be + (bias - mm) * sc;
    }
    __syncthreads();

    for (int task = tid; task < S_ * IC_ * P4_1; task += 256) {
        int q = task % P4_1;
        int i = (task / P4_1) % IC_;
        int s = task / (IC_ * P4_1);
        const float* wra = wab + (s * 32 + i) * C_;
        const float* wrb = wab + (s * 32 + 16 + i) * C_;
        const float* xq  = xs + q * 4;
        float4 A = {0, 0, 0, 0};
        float4 B = {0, 0, 0, 0};
        #pragma unroll
        for (int c4 = 0; c4 < 16; ++c4) {
            float4 w4a = *(const float4*)(wra + c4 * 4);
            float4 w4b = *(const float4*)(wrb + c4 * 4);
            float4 x0 = *(const float4*)(xq + (c4 * 4 + 0) * PTS1);
            float4 x1 = *(const float4*)(xq + (c4 * 4 + 1) * PTS1);
            float4 x2 = *(const float4*)(xq + (c4 * 4 + 2) * PTS1);
            float4 x3 = *(const float4*)(xq + (c4 * 4 + 3) * PTS1);
            A.x = fmaf(w4a.x, x0.x, A.x); A.y = fmaf(w4a.x, x0.y, A.y);
            A.z = fmaf(w4a.x, x0.z, A.z); A.w = fmaf(w4a.x, x0.w, A.w);
            A.x = fmaf(w4a.y, x1.x, A.x); A.y = fmaf(w4a.y, x1.y, A.y);
            A.z = fmaf(w4a.y, x1.z, A.z); A.w = fmaf(w4a.y, x1.w, A.w);
            A.x = fmaf(w4a.z, x2.x, A.x); A.y = fmaf(w4a.z, x2.y, A.y);
            A.z = fmaf(w4a.z, x2.z, A.z); A.w = fmaf(w4a.z, x2.w, A.w);
            A.x = fmaf(w4a.w, x3.x, A.x); A.y = fmaf(w4a.w, x3.y, A.y);
            A.z = fmaf(w4a.w, x3.z, A.z); A.w = fmaf(w4a.w, x3.w, A.w);
            B.x = fmaf(w4b.x, x0.x, B.x); B.y = fmaf(w4b.x, x0.y, B.y);
            B.z = fmaf(w4b.x, x0.z, B.z); B.w = fmaf(w4b.x, x0.w, B.w);
            B.x = fmaf(w4b.y, x1.x, B.x); B.y = fmaf(w4b.y, x1.y, B.y);
            B.z = fmaf(w4b.y, x1.z, B.z); B.w = fmaf(w4b.y, x1.w, B.w);
            B.x = fmaf(w4b.z, x2.x, B.x); B.y = fmaf(w4b.z, x2.y, B.y);
            B.z = fmaf(w4b.z, x2.z, B.z); B.w = fmaf(w4b.z, x2.w, B.w);
            B.x = fmaf(w4b.w, x3.x, B.x); B.y = fmaf(w4b.w, x3.y, B.y);
            B.z = fmaf(w4b.w, x3.z, B.z); B.w = fmaf(w4b.w, x3.w, B.w);
        }
        float mu, ad;
        float4 r;
        mu = mulc[s * 32 + i]; ad = addc[s * 32 + i];
        r.x = tanh_fast(fmaf(A.x, mu, ad)); r.y = tanh_fast(fmaf(A.y, mu, ad));
        r.z = tanh_fast(fmaf(A.z, mu, ad)); r.w = tanh_fast(fmaf(A.w, mu, ad));
        *(float4*)(ab + (s * 32 + i) * PTS1 + q * 4) = r;
        mu = mulc[s * 32 + 16 + i]; ad = addc[s * 32 + 16 + i];
        r.x = tanh_fast(fmaf(B.x, mu, ad)); r.y = tanh_fast(fmaf(B.y, mu, ad));
        r.z = tanh_fast(fmaf(B.z, mu, ad)); r.w = tanh_fast(fmaf(B.w, mu, ad));
        *(float4*)(ab + (s * 32 + 16 + i) * PTS1 + q * 4) = r;
    }
    __syncthreads();

    float* dst = g_Mpart + (size_t)(n * NC1 + chunk) * (S_ * V_ * V_);
    for (int task = tid; task < S_ * 169; task += 256) {
        int s = task / 169, r = task % 169;
        int vg = r / 13, wg = r % 13;
        int v0 = vg * 2, w0 = wg * 2;
        int v1c = min(v0 + 1, 24), w1c = min(w0 + 1, 24);
        float m00 = 0, m01 = 0, m10 = 0, m11 = 0;
        const float* abs_ = ab + s * 3200;
        for (int i = 0; i < IC_; ++i) {
            const float* arow = abs_ + i * PTS1;
            const float* brow = abs_ + (16 + i) * PTS1;
            #pragma unroll
            for (int tl = 0; tl < TT1; ++tl) {
                int base = tl * V_;
                float a0 = arow[base + v0], a1 = arow[base + v1c];
                float b0 = brow[base + w0], b1 = brow[base + w1c];
                m00 = fmaf(a0, b0, m00); m01 = fmaf(a0, b1, m01);
                m10 = fmaf(a1, b0, m10); m11 = fmaf(a1, b1, m11);
            }
        }
        float* Ms = dst + s * 625;
        Ms[v0 * 25 + w0] = m00;
        if (w0 + 1 < 25) Ms[v0 * 25 + w0 + 1] = m01;
        if (v0 + 1 < 25) Ms[(v0 + 1) * 25 + w0] = m10;
        if (w0 + 1 < 25 && v0 + 1 < 25) Ms[(v0 + 1) * 25 + w0 + 1] = m11;
    }
}

// =====================================================================
// Kernel 2: reduce partial M -> A_adp; transpose Wd to [s][c][o] in tf32
// =====================================================================
__global__ void k2_aadp(const float* __restrict__ A, const float* __restrict__ alpha,
                        const float* __restrict__ wd)
{
    int gid = blockIdx.x * blockDim.x + threadIdx.x;
    if (gid < N_ * S_ * V_ * V_) {
        int n = gid / (S_ * V_ * V_);
        int r = gid % (S_ * V_ * V_);
        float sum = 0.0f;
        const float* src = g_Mpart + (size_t)n * NC1 * (S_ * V_ * V_) + r;
        #pragma unroll 5
        for (int ch = 0; ch < NC1; ++ch) sum += src[(size_t)ch * (S_ * V_ * V_)];
        float Mval = sum * (1.0f / 4800.0f);
        g_Aadp[gid] = A[r] + tanh_fast(Mval) * alpha[0];
    }
    if (gid < S_ * C_ * OC_) {
        int s = gid / (C_ * OC_);
        int rem = gid % (C_ * OC_);
        int c = rem / OC_, o = rem % OC_;
        g_wdT[gid] = to_tf32(wd[(s * OC_ + o) * C_ + c]);
    }
}

// =====================================================================
// Kernel 3: per (n, 5-t chunk):
//   phase U (SIMT fp32): us[c][p] = sum_v x[c,tl,v] * Aadp[s][v][w]  (tf32-stored)
//   phase MMA (tf32):    Y[o][p] += sum_c wds[c][o] * us[c][p]   (3 s-passes)
//   epilogue: BN + residual + relu
// =====================================================================
__global__ __launch_bounds__(256, 2)
void k3_main(const float* __restrict__ x,
             const float* __restrict__ dbias,
             const float* __restrict__ bng, const float* __restrict__ bnb,
             const float* __restrict__ bnm, const float* __restrict__ bnv,
             float* __restrict__ out)
{
    extern __shared__ float sm3[];
    float* xs  = sm3;               // 64 * 140 = 8960 (fp32 x tile, padded rows of 28)
    float* us  = xs + C_ * XSP;     // 64 * 136 = 8704 (B operand, tf32 bits)
    float* wds = us + C_ * USP;     // 64 * 72  = 4608 (A operand [k=c][o], tf32 bits)
    float* as  = wds + C_ * WDP;    // 640 (A_adp for current s, padded)
    float* scs = as + 640;          // 64
    float* shs = scs + OC_;         // 64
    // total 23040 floats = 92160 B

    const int n = blockIdx.y, chunk = blockIdx.x, tid = threadIdx.x;
    const int lane = tid & 31, warp = tid >> 5;

    // ---- load x tile (fp32): xs[c][tl*28 + v]
    const float* xbase = x + (size_t)n * (C_ * T_ * V_) + chunk * NN3;
    for (int idx = tid; idx < C_ * NN3; idx += 256) {
        int c = idx / NN3, p = idx % NN3;
        xs[c * XSP + (p / V_) * 28 + (p % V_)] = xbase[c * (T_ * V_) + p];
    }
    // zero pad columns of us [125..136) once (never written by U phase)
    for (int idx = tid; idx < C_ * (USP - NN3); idx += 256) {
        int c = idx / (USP - NN3), j = idx % (USP - NN3);
        us[c * USP + NN3 + j] = 0.0f;
    }
    if (tid < OC_) {
        float scv = bng[tid] * rsqrtf(bnv[tid] + EPS_);
        float dbsum = dbias[tid] + dbias[OC_ + tid] + dbias[2 * OC_ + tid];
        scs[tid] = scv;
        shs[tid] = bnb[tid] + (dbsum - bnm[tid]) * scv;
    }

    // U-phase task: c = tid/4, w-group g = tid%4 covering w0..w0+nw-1
    const int uc = tid >> 2, ug = tid & 3;
    const int w0 = (ug == 0) ? 0 : (1 + ug * 6);   // 0,7,13,19
    const int nw = (ug == 0) ? 7 : 6;

    // MMA accumulators: 4 m-tiles (o) x 2 n-tiles x 4 regs
    float cacc[4][2][4];
    #pragma unroll
    for (int mt = 0; mt < 4; ++mt)
        #pragma unroll
        for (int nt = 0; nt < 2; ++nt)
            #pragma unroll
            for (int r = 0; r < 4; ++r) cacc[mt][nt][r] = 0.0f;

    const float* adp = g_Aadp + (size_t)n * (S_ * V_ * V_);
    const int n0 = warp * 16;

    for (int s = 0; s < S_; ++s) {
        __syncthreads();   // us from previous s fully consumed; xs ready (s=0)
        // stage A operand (tf32 pre-converted) and A_adp for this s
        for (int idx = tid; idx < C_ * OC_; idx += 256) {
            int k = idx >> 6, o = idx & 63;
            wds[k * WDP + o] = g_wdT[s * C_ * OC_ + idx];
        }
        for (int idx = tid; idx < V_ * V_; idx += 256)
            as[idx] = adp[s * V_ * V_ + idx];
        __syncthreads();

        // ---- U phase: u[tl][j] = sum_v x[uc][tl][v] * as[v][w0+j]
        {
            float acc[TT3][7];
            #pragma unroll
            for (int tl = 0; tl < TT3; ++tl)
                #pragma unroll
                for (int j = 0; j < 7; ++j) acc[tl][j] = 0.0f;
            const float* xc = xs + uc * XSP;
            #pragma unroll
            for (int v = 0; v < V_; ++v) {
                float a[7];
                #pragma unroll
                for (int j = 0; j < 7; ++j) a[j] = as[v * V_ + w0 + j];  // as padded to 640
                #pragma unroll
                for (int tl = 0; tl < TT3; ++tl) {
                    float xv = xc[tl * 28 + v];
                    #pragma unroll
                    for (int j = 0; j < 7; ++j) acc[tl][j] = fmaf(xv, a[j], acc[tl][j]);
                }
            }
            #pragma unroll
            for (int tl = 0; tl < TT3; ++tl)
                for (int j = 0; j < nw; ++j)
                    us[uc * USP + tl * V_ + w0 + j] = to_tf32(acc[tl][j]);
        }
        __syncthreads();

        // ---- MMA phase: K = 64 (c), 8 k-steps of 8
        #pragma unroll
        for (int ks = 0; ks < 8; ++ks) {
            const int k0 = ks * 8;
            uint32_t af[4][4];
            const int ar0 = (k0 + (lane & 3)) * WDP + (lane >> 2);
            const int ar1 = ar0 + 4 * WDP;
            #pragma unroll
            for (int mt = 0; mt < 4; ++mt) {
                af[mt][0] = __float_as_uint(wds[ar0 + mt * 16]);
                af[mt][1] = __float_as_uint(wds[ar0 + mt * 16 + 8]);
                af[mt][2] = __float_as_uint(wds[ar1 + mt * 16]);
                af[mt][3] = __float_as_uint(wds[ar1 + mt * 16 + 8]);
            }
            uint32_t bf[2][2];
            const int br0 = (k0 + (lane & 3)) * USP + n0 + (lane >> 2);
            const int br1 = br0 + 4 * USP;
            #pragma unroll
            for (int nt = 0; nt < 2; ++nt) {
                bf[nt][0] = __float_as_uint(us[br0 + nt * 8]);
                bf[nt][1] = __float_as_uint(us[br1 + nt * 8]);
            }
            #pragma unroll
            for (int mt = 0; mt < 4; ++mt)
                #pragma unroll
                for (int nt = 0; nt < 2; ++nt)
                    mma_tf32(cacc[mt][nt], af[mt][0], af[mt][1], af[mt][2], af[mt][3],
                             bf[nt][0], bf[nt][1]);
        }
    }

    // ---- epilogue: BN + residual + relu, write out
    float* obase = out + (size_t)n * (C_ * T_ * V_) + chunk * NN3;
    #pragma unroll
    for (int mt = 0; mt < 4; ++mt) {
        #pragma unroll
        for (int nt = 0; nt < 2; ++nt) {
            #pragma unroll
            for (int half = 0; half < 2; ++half) {
                int o = mt * 16 + (lane >> 2) + half * 8;
                int pb = n0 + nt * 8 + (lane & 3) * 2;
                float sc = scs[o], sh = shs[o];
                #pragma unroll
                for (int e = 0; e < 2; ++e) {
                    int p = pb + e;
                    if (p < NN3) {
                        float val = fmaf(cacc[mt][nt][half * 2 + e], sc, sh)
                                  + xs[o * XSP + (p / V_) * 28 + (p % V_)];
                        obase[o * (T_ * V_) + p] = fmaxf(val, 0.0f);
                    }
                }
            }
        }
    }
}

// =====================================================================
extern "C" void kernel_launch(void* const* d_in, const int* in_sizes, int n_in,
                              void* d_out, int out_size)
{
    const float* x    = (const float*)d_in[0];
    const float* A    = (const float*)d_in[1];
    const float* alph = (const float*)d_in[2];
    const float* wa   = (const float*)d_in[3];
    const float* ba   = (const float*)d_in[4];
    const float* wb   = (const float*)d_in[5];
    const float* bb   = (const float*)d_in[6];
    const float* bag  = (const float*)d_in[7];
    const float* bab  = (const float*)d_in[8];
    const float* bam  = (const float*)d_in[9];
    const float* bav  = (const float*)d_in[10];
    const float* bbg  = (const float*)d_in[11];
    const float* bbb  = (const float*)d_in[12];
    const float* bbm  = (const float*)d_in[13];
    const float* bbv  = (const float*)d_in[14];
    const float* wd   = (const float*)d_in[15];
    const float* db   = (const float*)d_in[16];
    const float* bng  = (const float*)d_in[17];
    const float* bnbt = (const float*)d_in[18];
    const float* bnm  = (const float*)d_in[19];
    const float* bnv  = (const float*)d_in[20];
    float* out = (float*)d_out;

    const int SM1 = 22336 * (int)sizeof(float); // 89344 B
    const int SM3 = 23040 * (int)sizeof(float); // 92160 B
    cudaFuncSetAttribute(k1_mpart, cudaFuncAttributeMaxDynamicSharedMemorySize, SM1);
    cudaFuncSetAttribute(k3_main,  cudaFuncAttributeMaxDynamicSharedMemorySize, SM3);

    dim3 g1(NC1, N_);
    k1_mpart<<<g1, 256, SM1>>>(x, wa, ba, wb, bb, bag, bab, bam, bav, bbg, bbb, bbm, bbv);

    k2_aadp<<<(N_ * S_ * V_ * V_ + 255) / 256, 256>>>(A, alph, wd);

    dim3 g3(NC3, N_);
    k3_main<<<g3, 256, SM3>>>(x, db, bng, bnbt, bnm, bnv, out);
}

// round 4
// speedup vs baseline: 1.7870x; 1.0753x over previous
#include <cuda_runtime.h>
#include <cstdint>

#define N_ 64
#define C_ 64
#define T_ 300
#define V_ 25
#define S_ 3
#define IC_ 16
#define OC_ 64
#define EPS_ 1e-5f
#define TV_ (T_ * V_)

// both k1 and k3: 75 chunks of 4 timesteps, 100 cols per chunk
#define TT_ 4
#define NCH 75
#define PP 100

// ---- device-global scratch (no allocations allowed) ----
__device__ float g_Mpart[N_ * NCH * S_ * V_ * V_];
__device__ float g_Aadp[N_ * S_ * V_ * V_];
__device__ float g_wdT[S_ * C_ * OC_];               // [s][c][o], tf32

__device__ __forceinline__ float tanh_fast(float x) {
    float cx = fminf(fmaxf(x, -10.0f), 10.0f);
    float e = __expf(2.0f * cx);
    return __fdividef(e - 1.0f, e + 1.0f);
}

__device__ __forceinline__ float to_tf32(float x) {
    uint32_t u;
    asm("cvt.rna.tf32.f32 %0, %1;" : "=r"(u) : "f"(x));
    return __uint_as_float(u);
}

__device__ __forceinline__ void mma_tf32(float c[4],
                                         uint32_t a0, uint32_t a1, uint32_t a2, uint32_t a3,
                                         uint32_t b0, uint32_t b1) {
    asm volatile("mma.sync.aligned.m16n8k8.row.col.f32.tf32.tf32.f32 "
                 "{%0,%1,%2,%3}, {%4,%5,%6,%7}, {%8,%9}, {%0,%1,%2,%3};"
                 : "+f"(c[0]), "+f"(c[1]), "+f"(c[2]), "+f"(c[3])
                 : "r"(a0), "r"(a1), "r"(a2), "r"(a3), "r"(b0), "r"(b1));
}

// Validated fragment loaders: operand buffers laid out [k][m] / [k][n].
// A: af0=(r,k) af1=(r+8,k) af2=(r,k+4) af3=(r+8,k+4); B: b0=(k,n) b1=(k+4,n).
// C: element (half,e) -> row m0+(lane>>2)+half*8, col n0+(lane&3)*2+e.

// =====================================================================
// Kernel 1: per (n, 4-t chunk):
//  stage1 MMA: [96 x 100 x 64]  rows=(s, i, a|b), BN+tanh on fragments
//  stage2 MMA: per s, M[32x32x64] = a^T b -> gmem partials
// =====================================================================
#define K1P 104   // pitch for wab ([c][96->104]) and xs ([c][100->104])
#define STP 40    // pitch for ast/bst

__global__ __launch_bounds__(256, 2)
void k1_mpart(const float* __restrict__ x,
              const float* __restrict__ wa, const float* __restrict__ ba,
              const float* __restrict__ wb, const float* __restrict__ bb,
              const float* __restrict__ gaA, const float* __restrict__ beA,
              const float* __restrict__ mA,  const float* __restrict__ vA,
              const float* __restrict__ gaB, const float* __restrict__ beB,
              const float* __restrict__ mB,  const float* __restrict__ vB)
{
    extern __shared__ float sm1[];
    // stage2 buffers (used after the mid-kernel sync):
    float* ast  = sm1;           // 3 * 64 * 40 = 7680   [s][k=(i,tl)][v]
    float* bst  = sm1 + 7680;    // 3 * 64 * 40 = 7680   [s][k=(i,tl)][w]
    // stage1 buffers (overlaid):
    float* wab  = sm1;           // 64 * 104 = 6656      [c][r=96] tf32
    float* xs   = sm1 + 7680;    // 64 * 104 = 6656      [c][p=100] tf32
    float* mulc = sm1 + 15360;   // 96
    float* addc = mulc + 96;     // 96
    // total 15552 floats = 62208 B

    const int n = blockIdx.y, chunk = blockIdx.x, tid = threadIdx.x;
    const int lane = tid & 31, warp = tid >> 5;

    // ---- stage weights [c][r] tf32 (r = s*32 + j; j<16 -> wa_i, j>=16 -> wb_i)
    for (int idx = tid; idx < C_ * 96; idx += 256) {
        int c = idx / 96, r = idx % 96;
        int s = r >> 5, j = r & 31;
        float wv = (j < IC_) ? wa[(s * IC_ + j) * C_ + c]
                             : wb[(s * IC_ + (j - 16)) * C_ + c];
        wab[c * K1P + r] = to_tf32(wv);
    }
    // ---- stage x tile [c][p] tf32
    const float* xbase = x + (size_t)n * (C_ * TV_) + chunk * PP;
    for (int idx4 = tid; idx4 < C_ * (PP / 4); idx4 += 256) {
        int c = idx4 / 25, q = idx4 % 25;
        float4 v = *(const float4*)(xbase + c * TV_ + q * 4);
        v.x = to_tf32(v.x); v.y = to_tf32(v.y); v.z = to_tf32(v.z); v.w = to_tf32(v.w);
        *(float4*)(xs + c * K1P + q * 4) = v;
    }
    if (tid < 96) {
        int s = tid >> 5, j = tid & 31;
        int i = (j < IC_) ? j : j - 16;
        int off = s * IC_ + i;
        float g, be, mm, vv, bias;
        if (j < IC_) { g = gaA[off]; be = beA[off]; mm = mA[off]; vv = vA[off]; bias = ba[off]; }
        else         { g = gaB[off]; be = beB[off]; mm = mB[off]; vv = vB[off]; bias = bb[off]; }
        float sc = g * rsqrtf(vv + EPS_);
        mulc[tid] = sc;
        addc[tid] = be + (bias - mm) * sc;
    }
    __syncthreads();

    // ---- stage1 MMA: 6 m-tiles x 13 n-tiles = 78 pairs, K=64 (8 k-steps)
    float acc[10][4];
    #pragma unroll
    for (int t = 0; t < 10; ++t)
        #pragma unroll
        for (int r = 0; r < 4; ++r) acc[t][r] = 0.0f;

    #pragma unroll
    for (int ti = 0; ti < 10; ++ti) {
        int pair = warp + ti * 8;
        if (pair < 78) {
            int mt = pair / 13, nt = pair % 13;
            #pragma unroll
            for (int k0 = 0; k0 < 8; ++k0) {
                int kk = k0 * 8;
                int ar0 = (kk + (lane & 3)) * K1P + mt * 16 + (lane >> 2);
                int ar1 = ar0 + 4 * K1P;
                uint32_t a0 = __float_as_uint(wab[ar0]);
                uint32_t a1 = __float_as_uint(wab[ar0 + 8]);
                uint32_t a2 = __float_as_uint(wab[ar1]);
                uint32_t a3 = __float_as_uint(wab[ar1 + 8]);
                int br0 = (kk + (lane & 3)) * K1P + nt * 8 + (lane >> 2);
                uint32_t b0 = __float_as_uint(xs[br0]);
                uint32_t b1 = __float_as_uint(xs[br0 + 4 * K1P]);
                mma_tf32(acc[ti], a0, a1, a2, a3, b0, b1);
            }
        }
    }
    __syncthreads();   // done reading wab/xs; overlay region now writable

    // ---- BN + tanh on fragments, scatter to ast/bst (tf32)
    #pragma unroll
    for (int ti = 0; ti < 10; ++ti) {
        int pair = warp + ti * 8;
        if (pair < 78) {
            int mt = pair / 13, nt = pair % 13;
            #pragma unroll
            for (int half = 0; half < 2; ++half) {
                int r = mt * 16 + (lane >> 2) + half * 8;
                float mu = mulc[r], ad = addc[r];
                int s = r >> 5, j = r & 31;
                #pragma unroll
                for (int e = 0; e < 2; ++e) {
                    int p = nt * 8 + (lane & 3) * 2 + e;
                    if (p < PP) {
                        int tl = p / V_, v = p % V_;
                        float val = tanh_fast(fmaf(acc[ti][half * 2 + e], mu, ad));
                        int k = (j & 15) * TT_ + tl;
                        float* dstb = (j < IC_) ? ast : bst;
                        dstb[s * (64 * STP) + k * STP + v] = to_tf32(val);
                    }
                }
            }
        }
    }
    __syncthreads();

    // ---- stage2 MMA: 24 tasks = (s, mt(2), nt(4)), K=64
    float* dst = g_Mpart + (size_t)(n * NCH + chunk) * (S_ * V_ * V_);
    #pragma unroll
    for (int ti = 0; ti < 3; ++ti) {
        int task = warp + ti * 8;
        int s = task >> 3, mt = (task >> 2) & 1, nt = task & 3;
        float acc2[4] = {0.0f, 0.0f, 0.0f, 0.0f};
        const float* as_ = ast + s * (64 * STP);
        const float* bs_ = bst + s * (64 * STP);
        #pragma unroll
        for (int k0 = 0; k0 < 8; ++k0) {
            int kk = k0 * 8;
            int ar0 = (kk + (lane & 3)) * STP + mt * 16 + (lane >> 2);
            int ar1 = ar0 + 4 * STP;
            uint32_t a0 = __float_as_uint(as_[ar0]);
            uint32_t a1 = __float_as_uint(as_[ar0 + 8]);
            uint32_t a2 = __float_as_uint(as_[ar1]);
            uint32_t a3 = __float_as_uint(as_[ar1 + 8]);
            int br0 = (kk + (lane & 3)) * STP + nt * 8 + (lane >> 2);
            uint32_t b0 = __float_as_uint(bs_[br0]);
            uint32_t b1 = __float_as_uint(bs_[br0 + 4 * STP]);
            mma_tf32(acc2, a0, a1, a2, a3, b0, b1);
        }
        #pragma unroll
        for (int half = 0; half < 2; ++half) {
            int v = mt * 16 + (lane >> 2) + half * 8;
            #pragma unroll
            for (int e = 0; e < 2; ++e) {
                int w = nt * 8 + (lane & 3) * 2 + e;
                if (v < V_ && w < V_)
                    dst[s * 625 + v * 25 + w] = acc2[half * 2 + e];
            }
        }
    }
}

// =====================================================================
// Kernel 2: reduce partial M -> A_adp; transpose Wd to [s][c][o] tf32
// =====================================================================
__global__ void k2_aadp(const float* __restrict__ A, const float* __restrict__ alpha,
                        const float* __restrict__ wd)
{
    int gid = blockIdx.x * blockDim.x + threadIdx.x;
    if (gid < N_ * S_ * V_ * V_) {
        int n = gid / (S_ * V_ * V_);
        int r = gid % (S_ * V_ * V_);
        float sum = 0.0f;
        const float* src = g_Mpart + (size_t)n * NCH * (S_ * V_ * V_) + r;
        #pragma unroll 5
        for (int ch = 0; ch < NCH; ++ch) sum += src[(size_t)ch * (S_ * V_ * V_)];
        float Mval = sum * (1.0f / 4800.0f);
        g_Aadp[gid] = A[r] + tanh_fast(Mval) * alpha[0];
    }
    if (gid < S_ * C_ * OC_) {
        int s = gid / (C_ * OC_);
        int rem = gid % (C_ * OC_);
        int c = rem / OC_, o = rem % OC_;
        g_wdT[gid] = to_tf32(wd[(s * OC_ + o) * C_ + c]);
    }
}

// =====================================================================
// Kernel 3: per (n, 4-t chunk):
//  phase1 MMA (per s): U[(c,tl), w] = X[(c,tl), v] * Aadp[v][w]  (m=256,n=32,k=32)
//  phase2 MMA (per s): Y[o][p] += WdT[c][o]^T US[c][p]           (m=64,n=104,k=64)
//  epilogue: BN + residual(from gmem) + relu
// =====================================================================
#define XTP 264   // xsT pitch: [v:32][(c,tl):256->264] tf32
#define ASP 40    // as3 pitch: [s][v:32][w:25->40] tf32
#define USP 104   // us pitch:  [c][p:100->104] tf32
#define WDP 72    // wds pitch: [c][o:64->72] tf32

__global__ __launch_bounds__(256, 2)
void k3_main(const float* __restrict__ x,
             const float* __restrict__ dbias,
             const float* __restrict__ bng, const float* __restrict__ bnb,
             const float* __restrict__ bnm, const float* __restrict__ bnv,
             float* __restrict__ out)
{
    extern __shared__ float sm3[];
    float* xsT = sm3;            // 32 * 264 = 8448
    float* as3 = sm3 + 8448;     // 3 * 32 * 40 = 3840
    float* us  = sm3 + 12288;    // 64 * 104 = 6656
    float* wds = sm3 + 18944;    // 64 * 72 = 4608
    float* scs = sm3 + 23552;    // 64
    float* shs = sm3 + 23616;    // 64
    // total 23680 floats = 94720 B

    const int n = blockIdx.y, chunk = blockIdx.x, tid = threadIdx.x;
    const int lane = tid & 31, warp = tid >> 5;

    const float* xbase = x + (size_t)n * (C_ * TV_) + chunk * PP;

    // ---- stage xsT (tf32, transposed) + zero v-pad rows; zero as3
    for (int idx = tid; idx < C_ * PP; idx += 256) {
        int c = idx / PP, p = idx % PP;
        xsT[(p % V_) * XTP + c * TT_ + (p / V_)] = to_tf32(xbase[c * TV_ + p]);
    }
    for (int idx = tid; idx < 7 * XTP; idx += 256) xsT[25 * XTP + idx] = 0.0f;
    for (int idx = tid; idx < 3 * 32 * ASP; idx += 256) as3[idx] = 0.0f;
    if (tid < OC_) {
        float scv = bng[tid] * rsqrtf(bnv[tid] + EPS_);
        float dbsum = dbias[tid] + dbias[OC_ + tid] + dbias[2 * OC_ + tid];
        scs[tid] = scv;
        shs[tid] = bnb[tid] + (dbsum - bnm[tid]) * scv;
    }
    __syncthreads();
    // ---- fill as3 (tf32)
    const float* adp = g_Aadp + (size_t)n * (S_ * V_ * V_);
    for (int idx = tid; idx < S_ * V_ * V_; idx += 256) {
        int s = idx / 625, r = idx % 625;
        as3[s * (32 * ASP) + (r / V_) * ASP + (r % V_)] = to_tf32(adp[idx]);
    }

    float accY[7][4];
    #pragma unroll
    for (int t = 0; t < 7; ++t)
        #pragma unroll
        for (int r = 0; r < 4; ++r) accY[t][r] = 0.0f;

    for (int s = 0; s < S_; ++s) {
        __syncthreads();  // prev phase2 done (us/wds consumable); as3 fill done (s=0)
        // stage wds for this s (already tf32 in gmem)
        for (int idx = tid; idx < C_ * OC_; idx += 256)
            wds[(idx >> 6) * WDP + (idx & 63)] = g_wdT[s * C_ * OC_ + idx];

        // phase1: 16 m-tiles x 4 n-tiles = 64 pairs, K=32 (4 k-steps)
        const float* ass = as3 + s * (32 * ASP);
        #pragma unroll
        for (int ti = 0; ti < 8; ++ti) {
            int pair = warp + ti * 8;
            int mt = pair >> 2, nt = pair & 3;
            float acc1[4] = {0.0f, 0.0f, 0.0f, 0.0f};
            #pragma unroll
            for (int k0 = 0; k0 < 4; ++k0) {
                int kk = k0 * 8;
                int ar0 = (kk + (lane & 3)) * XTP + mt * 16 + (lane >> 2);
                int ar1 = ar0 + 4 * XTP;
                uint32_t a0 = __float_as_uint(xsT[ar0]);
                uint32_t a1 = __float_as_uint(xsT[ar0 + 8]);
                uint32_t a2 = __float_as_uint(xsT[ar1]);
                uint32_t a3 = __float_as_uint(xsT[ar1 + 8]);
                int br0 = (kk + (lane & 3)) * ASP + nt * 8 + (lane >> 2);
                uint32_t b0 = __float_as_uint(ass[br0]);
                uint32_t b1 = __float_as_uint(ass[br0 + 4 * ASP]);
                mma_tf32(acc1, a0, a1, a2, a3, b0, b1);
            }
            // scatter U fragments -> us[c][p] (tf32)
            #pragma unroll
            for (int half = 0; half < 2; ++half) {
                int m = mt * 16 + (lane >> 2) + half * 8;
                int c = m >> 2, tl = m & 3;
                #pragma unroll
                for (int e = 0; e < 2; ++e) {
                    int w = nt * 8 + (lane & 3) * 2 + e;
                    if (w < V_)
                        us[c * USP + tl * V_ + w] = to_tf32(acc1[half * 2 + e]);
                }
            }
        }
        __syncthreads();

        // phase2: 4 m-tiles x 13 n-tiles = 52 pairs, K=64 (8 k-steps)
        #pragma unroll
        for (int ti = 0; ti < 7; ++ti) {
            int pair = warp + ti * 8;
            if (pair < 52) {
                int mt = pair / 13, nt = pair % 13;
                #pragma unroll
                for (int k0 = 0; k0 < 8; ++k0) {
                    int kk = k0 * 8;
                    int ar0 = (kk + (lane & 3)) * WDP + mt * 16 + (lane >> 2);
                    int ar1 = ar0 + 4 * WDP;
                    uint32_t a0 = __float_as_uint(wds[ar0]);
                    uint32_t a1 = __float_as_uint(wds[ar0 + 8]);
                    uint32_t a2 = __float_as_uint(wds[ar1]);
                    uint32_t a3 = __float_as_uint(wds[ar1 + 8]);
                    int br0 = (kk + (lane & 3)) * USP + nt * 8 + (lane >> 2);
                    uint32_t b0 = __float_as_uint(us[br0]);
                    uint32_t b1 = __float_as_uint(us[br0 + 4 * USP]);
                    mma_tf32(accY[ti], a0, a1, a2, a3, b0, b1);
                }
            }
        }
    }

    // ---- epilogue: BN + residual + relu
    float* obase = out + (size_t)n * (C_ * TV_) + chunk * PP;
    #pragma unroll
    for (int ti = 0; ti < 7; ++ti) {
        int pair = warp + ti * 8;
        if (pair < 52) {
            int mt = pair / 13, nt = pair % 13;
            #pragma unroll
            for (int half = 0; half < 2; ++half) {
                int o = mt * 16 + (lane >> 2) + half * 8;
                float sc = scs[o], sh = shs[o];
                #pragma unroll
                for (int e = 0; e < 2; ++e) {
                    int p = nt * 8 + (lane & 3) * 2 + e;
                    if (p < PP) {
                        float res = xbase[o * TV_ + p];  // fp32 residual (cache-hot)
                        float val = fmaf(accY[ti][half * 2 + e], sc, sh) + res;
                        obase[o * TV_ + p] = fmaxf(val, 0.0f);
                    }
                }
            }
        }
    }
}

// =====================================================================
extern "C" void kernel_launch(void* const* d_in, const int* in_sizes, int n_in,
                              void* d_out, int out_size)
{
    const float* x    = (const float*)d_in[0];
    const float* A    = (const float*)d_in[1];
    const float* alph = (const float*)d_in[2];
    const float* wa   = (const float*)d_in[3];
    const float* ba   = (const float*)d_in[4];
    const float* wb   = (const float*)d_in[5];
    const float* bb   = (const float*)d_in[6];
    const float* bag  = (const float*)d_in[7];
    const float* bab  = (const float*)d_in[8];
    const float* bam  = (const float*)d_in[9];
    const float* bav  = (const float*)d_in[10];
    const float* bbg  = (const float*)d_in[11];
    const float* bbb  = (const float*)d_in[12];
    const float* bbm  = (const float*)d_in[13];
    const float* bbv  = (const float*)d_in[14];
    const float* wd   = (const float*)d_in[15];
    const float* db   = (const float*)d_in[16];
    const float* bng  = (const float*)d_in[17];
    const float* bnbt = (const float*)d_in[18];
    const float* bnm  = (const float*)d_in[19];
    const float* bnv  = (const float*)d_in[20];
    float* out = (float*)d_out;

    const int SM1 = 15552 * (int)sizeof(float); // 62208 B
    const int SM3 = 23680 * (int)sizeof(float); // 94720 B
    cudaFuncSetAttribute(k1_mpart, cudaFuncAttributeMaxDynamicSharedMemorySize, SM1);
    cudaFuncSetAttribute(k3_main,  cudaFuncAttributeMaxDynamicSharedMemorySize, SM3);

    dim3 g(NCH, N_);
    k1_mpart<<<g, 256, SM1>>>(x, wa, ba, wb, bb, bag, bab, bam, bav, bbg, bbb, bbm, bbv);

    k2_aadp<<<(N_ * S_ * V_ * V_ + 255) / 256, 256>>>(A, alph, wd);

    k3_main<<<g, 256, SM3>>>(x, db, bng, bnbt, bnm, bnv, out);
}

// round 6
// speedup vs baseline: 2.8522x; 1.5961x over previous
#include <cuda_runtime.h>
#include <cstdint>

#define N_ 64
#define C_ 64
#define T_ 300
#define V_ 25
#define S_ 3
#define IC_ 16
#define OC_ 64
#define EPS_ 1e-5f
#define TV_ (T_ * V_)

#define TT_ 4
#define NCH 75
#define PP 100

#define K1P 104   // wab/xs pitch
#define STP 40    // ast/bst pitch (swizzled cols)
#define XTP 264   // xsT pitch
#define ASP 40    // as3 pitch
#define USP 104   // us pitch
#define WDP 72    // g_wdT72 pitch

// ---- device-global scratch ----
__device__ float g_Mpart[N_ * NCH * S_ * V_ * V_];
__device__ float g_Aadp[N_ * S_ * 32 * ASP];        // padded tf32 [n][s][v:32][40]
__device__ float g_wabT[C_ * K1P];                  // [c][r:96 pad 104] tf32
__device__ float g_wdT72[S_ * C_ * WDP];            // [s][c][o:64 pad 72] tf32
__device__ float g_bnc[192];                        // mulc[96], addc[96]
__device__ float g_obnc[128];                       // scs[64], shs[64]

__device__ __forceinline__ float tanh_fast(float x) {
    float cx = fminf(fmaxf(x, -10.0f), 10.0f);
    float e = __expf(2.0f * cx);
    return __fdividef(e - 1.0f, e + 1.0f);
}
__device__ __forceinline__ float to_tf32(float x) {
    uint32_t u;
    asm("cvt.rna.tf32.f32 %0, %1;" : "=r"(u) : "f"(x));
    return __uint_as_float(u);
}
__device__ __forceinline__ void mma_tf32(float c[4],
                                         uint32_t a0, uint32_t a1, uint32_t a2, uint32_t a3,
                                         uint32_t b0, uint32_t b1) {
    asm volatile("mma.sync.aligned.m16n8k8.row.col.f32.tf32.tf32.f32 "
                 "{%0,%1,%2,%3}, {%4,%5,%6,%7}, {%8,%9}, {%0,%1,%2,%3};"
                 : "+f"(c[0]), "+f"(c[1]), "+f"(c[2]), "+f"(c[3])
                 : "r"(a0), "r"(a1), "r"(a2), "r"(a3), "r"(b0), "r"(b1));
}

// =====================================================================
// k0: one-time prep of weight layouts + BN constants
// =====================================================================
__global__ void k0_prep(const float* __restrict__ wa, const float* __restrict__ ba,
                        const float* __restrict__ wb, const float* __restrict__ bb,
                        const float* __restrict__ gaA, const float* __restrict__ beA,
                        const float* __restrict__ mA,  const float* __restrict__ vA,
                        const float* __restrict__ gaB, const float* __restrict__ beB,
                        const float* __restrict__ mB,  const float* __restrict__ vB,
                        const float* __restrict__ wd,  const float* __restrict__ dbias,
                        const float* __restrict__ bng, const float* __restrict__ bnb,
                        const float* __restrict__ bnm, const float* __restrict__ bnv)
{
    int gid = blockIdx.x * blockDim.x + threadIdx.x;
    if (gid < C_ * K1P) {
        int c = gid / K1P, r = gid % K1P;
        float val = 0.0f;
        if (r < 96) {
            int s = r >> 5, j = r & 31;
            val = (j < IC_) ? wa[(s * IC_ + j) * C_ + c]
                            : wb[(s * IC_ + (j - 16)) * C_ + c];
            val = to_tf32(val);
        }
        g_wabT[gid] = val;
        return;
    }
    int g2 = gid - C_ * K1P;
    if (g2 < S_ * C_ * WDP) {
        int s = g2 / (C_ * WDP);
        int rem = g2 % (C_ * WDP);
        int c = rem / WDP, o = rem % WDP;
        g_wdT72[g2] = (o < OC_) ? to_tf32(wd[(s * OC_ + o) * C_ + c]) : 0.0f;
        return;
    }
    int g3 = g2 - S_ * C_ * WDP;
    if (g3 < 96) {
        int s = g3 >> 5, j = g3 & 31;
        int i = (j < IC_) ? j : j - 16;
        int off = s * IC_ + i;
        float g, be, mm, vv, bias;
        if (j < IC_) { g = gaA[off]; be = beA[off]; mm = mA[off]; vv = vA[off]; bias = ba[off]; }
        else         { g = gaB[off]; be = beB[off]; mm = mB[off]; vv = vB[off]; bias = bb[off]; }
        float sc = g * rsqrtf(vv + EPS_);
        g_bnc[g3] = sc;
        g_bnc[96 + g3] = be + (bias - mm) * sc;
        return;
    }
    int g4 = g3 - 96;
    if (g4 < 96 + 128 && g4 >= 96) {
        int t = g4 - 96;
        if (t < OC_) {
            float scv = bng[t] * rsqrtf(bnv[t] + EPS_);
            g_obnc[t] = scv;
            g_obnc[64 + t] = bnb[t] + (dbias[t] + dbias[OC_ + t] + dbias[2 * OC_ + t] - bnm[t]) * scv;
        }
    }
}

// =====================================================================
// k1: per (n, 4-t chunk): stage1 strip-MMA conv+BN+tanh, swizzled scatter,
// stage2 MMA M partials -> gmem
// =====================================================================
__global__ __launch_bounds__(256, 2)
void k1_mpart(const float* __restrict__ x)
{
    extern __shared__ float sm1[];
    float* ast = sm1;            // 3*64*40 = 7680 (overlay wab)
    float* bst = sm1 + 7680;     // 7680 (overlay xs)
    float* wab = sm1;            // 64*104 = 6656
    float* xs  = sm1 + 7680;     // 64*104 = 6656
    // total 15360 floats = 61440 B

    const int n = blockIdx.y, chunk = blockIdx.x, tid = threadIdx.x;
    const int lane = tid & 31, warp = tid >> 5;
    const int qk = lane & 3, qm = lane >> 2;

    // ---- staging: pure linear copies
    for (int idx = tid; idx < (C_ * K1P) / 4; idx += 256)
        *(float4*)(wab + idx * 4) = *(const float4*)(g_wabT + idx * 4);
    const float* xbase = x + (size_t)n * (C_ * TV_) + chunk * PP;
    for (int idx = tid; idx < C_ * (PP / 4); idx += 256) {
        int c = idx / 25, q = idx % 25;   // small const-div
        *(float4*)(xs + c * K1P + q * 4) = *(const float4*)(xbase + c * TV_ + q * 4);
    }
    __syncthreads();

    // ---- stage1: warps 0..5 each own m-strip mt=warp; 13 nt, K=64
    float acc[13][4];
    if (warp < 6) {
        #pragma unroll
        for (int t = 0; t < 13; ++t)
            #pragma unroll
            for (int r = 0; r < 4; ++r) acc[t][r] = 0.0f;
        const int mt = warp;
        #pragma unroll
        for (int k0 = 0; k0 < 8; ++k0) {
            int row = k0 * 8 + qk;
            int ab0 = row * K1P + mt * 16 + qm;
            uint32_t a0 = __float_as_uint(wab[ab0]);
            uint32_t a1 = __float_as_uint(wab[ab0 + 8]);
            uint32_t a2 = __float_as_uint(wab[ab0 + 4 * K1P]);
            uint32_t a3 = __float_as_uint(wab[ab0 + 4 * K1P + 8]);
            int bb0 = row * K1P + qm;
            #pragma unroll
            for (int nt = 0; nt < 13; ++nt) {
                uint32_t b0 = __float_as_uint(xs[bb0 + nt * 8]);
                uint32_t b1 = __float_as_uint(xs[bb0 + nt * 8 + 4 * K1P]);
                mma_tf32(acc[nt], a0, a1, a2, a3, b0, b1);
            }
        }
    }
    __syncthreads();   // wab/xs free; ast/bst writable

    // ---- BN + tanh on fragments, swizzled scatter to ast/bst
    if (warp < 6) {
        const int mt = warp;
        #pragma unroll
        for (int half = 0; half < 2; ++half) {
            int r = mt * 16 + qm + half * 8;
            float mu = g_bnc[r], ad = g_bnc[96 + r];
            int s = r >> 5, j = r & 31, i = j & 15;
            float* dstb = (j < IC_) ? ast : bst;
            dstb += s * (64 * STP);
            int gsw = (i & 3) << 3;
            int v = qk * 2, tl = 0;
            #pragma unroll
            for (int nt = 0; nt < 13; ++nt) {
                // e = 0
                if (tl < TT_) {
                    float val = tanh_fast(fmaf(acc[nt][half * 2], mu, ad));
                    dstb[(i * TT_ + tl) * STP + (v ^ gsw)] = val;
                }
                // e = 1
                int v1 = v + 1, tl1 = tl;
                if (v1 == 25) { v1 = 0; tl1 = tl + 1; }
                if (tl1 < TT_) {
                    float val = tanh_fast(fmaf(acc[nt][half * 2 + 1], mu, ad));
                    dstb[(i * TT_ + tl1) * STP + (v1 ^ gsw)] = val;
                }
                v += 8;
                if (v >= 25) { v -= 25; tl += 1; }
            }
        }
    }
    __syncthreads();

    // ---- stage2: 24 tasks (s, mtv, ntw), 3 per warp, K=64, swizzled loads
    float* dst = g_Mpart + (size_t)(n * NCH + chunk) * (S_ * V_ * V_);
    #pragma unroll
    for (int ti = 0; ti < 3; ++ti) {
        int task = warp * 3 + ti;
        int s = task >> 3, mtv = (task >> 2) & 1, ntw = task & 3;
        const float* as_ = ast + s * (64 * STP);
        const float* bs_ = bst + s * (64 * STP);
        float acc2[4] = {0.0f, 0.0f, 0.0f, 0.0f};
        #pragma unroll
        for (int k0 = 0; k0 < 8; ++k0) {
            int row0 = k0 * 8 + qk, row1 = row0 + 4;
            int g0 = ((row0 >> 2) & 3) << 3, g1 = ((row1 >> 2) & 3) << 3;
            int ca = mtv * 16 + qm, cb = ntw * 8 + qm;
            uint32_t a0 = __float_as_uint(as_[row0 * STP + (ca ^ g0)]);
            uint32_t a1 = __float_as_uint(as_[row0 * STP + ((ca + 8) ^ g0)]);
            uint32_t a2 = __float_as_uint(as_[row1 * STP + (ca ^ g1)]);
            uint32_t a3 = __float_as_uint(as_[row1 * STP + ((ca + 8) ^ g1)]);
            uint32_t b0 = __float_as_uint(bs_[row0 * STP + (cb ^ g0)]);
            uint32_t b1 = __float_as_uint(bs_[row1 * STP + (cb ^ g1)]);
            mma_tf32(acc2, a0, a1, a2, a3, b0, b1);
        }
        #pragma unroll
        for (int half = 0; half < 2; ++half) {
            int v = mtv * 16 + qm + half * 8;
            #pragma unroll
            for (int e = 0; e < 2; ++e) {
                int w = ntw * 8 + qk * 2 + e;
                if (v < V_ && w < V_)
                    dst[s * 625 + v * 25 + w] = acc2[half * 2 + e];
            }
        }
    }
}

// =====================================================================
// k2: reduce partial M -> A_adp in padded tf32 layout [n][s][32][40]
// =====================================================================
__global__ void k2_aadp(const float* __restrict__ A, const float* __restrict__ alpha)
{
    int gid = blockIdx.x * blockDim.x + threadIdx.x;
    if (gid >= N_ * S_ * 32 * ASP) return;
    int n = gid / (S_ * 32 * ASP);
    int rem = gid % (S_ * 32 * ASP);
    int s = rem / (32 * ASP);
    int r = rem % (32 * ASP);
    int v = r / ASP, w = r % ASP;
    float val = 0.0f;
    if (v < V_ && w < V_) {
        const float* src = g_Mpart + (size_t)n * NCH * (S_ * V_ * V_) + s * 625 + v * 25 + w;
        float sum = 0.0f;
        #pragma unroll 5
        for (int ch = 0; ch < NCH; ++ch) sum += src[(size_t)ch * (S_ * V_ * V_)];
        val = to_tf32(A[s * 625 + v * 25 + w] + tanh_fast(sum * (1.0f / 4800.0f)) * alpha[0]);
    }
    g_Aadp[gid] = val;
}

// =====================================================================
// k3: per (n, 4-t chunk):
//  phase1: U = X^T-tiles x Aadp (m=256,n=32,k=32), scatter to us
//  phase2: Y += WdT(gmem) x us (m=64,n=104,k=64)
//  epilogue: BN + residual + relu
// =====================================================================
__global__ __launch_bounds__(256, 3)
void k3_main(const float* __restrict__ x, float* __restrict__ out)
{
    extern __shared__ float sm3[];
    float* xsT = sm3;            // 32*264 = 8448
    float* as3 = sm3 + 8448;     // 3*32*40 = 3840
    float* us  = sm3 + 12288;    // 64*104 = 6656
    // total 18944 floats = 75776 B  -> 3 CTAs/SM

    const int n = blockIdx.y, chunk = blockIdx.x, tid = threadIdx.x;
    const int lane = tid & 31, warp = tid >> 5;
    const int qk = lane & 3, qm = lane >> 2;

    const float* xbase = x + (size_t)n * (C_ * TV_) + chunk * PP;

    // ---- stage xsT: conflict-free STS, LDG transposed (L1 absorbs)
    {
        int c = tid >> 2, tl = tid & 3;
        const float* xr = xbase + c * TV_ + tl * V_;
        #pragma unroll
        for (int v = 0; v < V_; ++v)
            xsT[v * XTP + tid] = xr[v];
    }
    for (int idx = tid; idx < 7 * XTP; idx += 256) xsT[25 * XTP + idx] = 0.0f;
    // ---- stage as3: linear float4 copy (already padded tf32)
    {
        const float4* src = (const float4*)(g_Aadp + (size_t)n * (S_ * 32 * ASP));
        for (int idx = tid; idx < (S_ * 32 * ASP) / 4; idx += 256)
            ((float4*)as3)[idx] = src[idx];
    }
    __syncthreads();

    // phase2 accumulators: warp owns mtY = warp>>1, nt range
    const int mtY = warp >> 1;
    const int ntb = (warp & 1) ? 7 : 0;
    const int nnt = (warp & 1) ? 6 : 7;
    float accY[7][4];
    #pragma unroll
    for (int t = 0; t < 7; ++t)
        #pragma unroll
        for (int r = 0; r < 4; ++r) accY[t][r] = 0.0f;

    for (int s = 0; s < S_; ++s) {
        // ---- phase1: warp owns mts {warp, warp+8}, all 4 nt, K=32
        {
            float acc1[2][4][4];
            #pragma unroll
            for (int m2 = 0; m2 < 2; ++m2)
                #pragma unroll
                for (int t = 0; t < 4; ++t)
                    #pragma unroll
                    for (int r = 0; r < 4; ++r) acc1[m2][t][r] = 0.0f;
            const float* ass = as3 + s * (32 * ASP);
            #pragma unroll
            for (int k0 = 0; k0 < 4; ++k0) {
                int row = k0 * 8 + qk;
                uint32_t a[2][4];
                #pragma unroll
                for (int m2 = 0; m2 < 2; ++m2) {
                    int base = row * XTP + (warp + m2 * 8) * 16 + qm;
                    a[m2][0] = __float_as_uint(xsT[base]);
                    a[m2][1] = __float_as_uint(xsT[base + 8]);
                    a[m2][2] = __float_as_uint(xsT[base + 4 * XTP]);
                    a[m2][3] = __float_as_uint(xsT[base + 4 * XTP + 8]);
                }
                #pragma unroll
                for (int nt = 0; nt < 4; ++nt) {
                    uint32_t b0 = __float_as_uint(ass[row * ASP + nt * 8 + qm]);
                    uint32_t b1 = __float_as_uint(ass[(row + 4) * ASP + nt * 8 + qm]);
                    #pragma unroll
                    for (int m2 = 0; m2 < 2; ++m2)
                        mma_tf32(acc1[m2][nt], a[m2][0], a[m2][1], a[m2][2], a[m2][3], b0, b1);
                }
            }
            // scatter U -> us[c][tl*25+w]
            #pragma unroll
            for (int m2 = 0; m2 < 2; ++m2) {
                #pragma unroll
                for (int half = 0; half < 2; ++half) {
                    int m = (warp + m2 * 8) * 16 + qm + half * 8;
                    int c = m >> 2, tl = m & 3;
                    float* ur = us + c * USP + tl * V_;
                    #pragma unroll
                    for (int nt = 0; nt < 4; ++nt) {
                        #pragma unroll
                        for (int e = 0; e < 2; ++e) {
                            int w = nt * 8 + qk * 2 + e;
                            if (w < V_) ur[w] = acc1[m2][nt][half * 2 + e];
                        }
                    }
                }
            }
        }
        __syncthreads();

        // ---- phase2: A from gmem (L1-hot), B from us, K=64
        const float* wdb = g_wdT72 + s * (C_ * WDP) + mtY * 16 + qm;
        #pragma unroll
        for (int k0 = 0; k0 < 8; ++k0) {
            int row = k0 * 8 + qk;
            const float* wr = wdb + row * WDP;
            uint32_t a0 = __float_as_uint(wr[0]);
            uint32_t a1 = __float_as_uint(wr[8]);
            uint32_t a2 = __float_as_uint(wr[4 * WDP]);
            uint32_t a3 = __float_as_uint(wr[4 * WDP + 8]);
            const float* ub0 = us + row * USP + qm;
            const float* ub1 = ub0 + 4 * USP;
            #pragma unroll
            for (int j = 0; j < 7; ++j) {
                if (j < nnt) {
                    int nt = ntb + j;
                    uint32_t b0 = __float_as_uint(ub0[nt * 8]);
                    uint32_t b1 = __float_as_uint(ub1[nt * 8]);
                    mma_tf32(accY[j], a0, a1, a2, a3, b0, b1);
                }
            }
        }
        __syncthreads();   // us consumed; next s may overwrite
    }

    // ---- epilogue: BN + residual + relu
    float* obase = out + (size_t)n * (C_ * TV_) + chunk * PP;
    #pragma unroll
    for (int half = 0; half < 2; ++half) {
        int o = mtY * 16 + qm + half * 8;
        float sc = g_obnc[o], sh = g_obnc[64 + o];
        const float* xr = xbase + o * TV_;
        float* orow = obase + o * TV_;
        #pragma unroll
        for (int j = 0; j < 7; ++j) {
            if (j < nnt) {
                int nt = ntb + j;
                #pragma unroll
                for (int e = 0; e < 2; ++e) {
                    int p = nt * 8 + qk * 2 + e;
                    if (p < PP) {
                        float val = fmaf(accY[j][half * 2 + e], sc, sh) + xr[p];
                        orow[p] = fmaxf(val, 0.0f);
                    }
                }
            }
        }
    }
}

// =====================================================================
extern "C" void kernel_launch(void* const* d_in, const int* in_sizes, int n_in,
                              void* d_out, int out_size)
{
    const float* x    = (const float*)d_in[0];
    const float* A    = (const float*)d_in[1];
    const float* alph = (const float*)d_in[2];
    const float* wa   = (const float*)d_in[3];
    const float* ba   = (const float*)d_in[4];
    const float* wb   = (const float*)d_in[5];
    const float* bb   = (const float*)d_in[6];
    const float* bag  = (const float*)d_in[7];
    const float* bab  = (const float*)d_in[8];
    const float* bam  = (const float*)d_in[9];
    const float* bav  = (const float*)d_in[10];
    const float* bbg  = (const float*)d_in[11];
    const float* bbb  = (const float*)d_in[12];
    const float* bbm  = (const float*)d_in[13];
    const float* bbv  = (const float*)d_in[14];
    const float* wd   = (const float*)d_in[15];
    const float* db   = (const float*)d_in[16];
    const float* bng  = (const float*)d_in[17];
    const float* bnbt = (const float*)d_in[18];
    const float* bnm  = (const float*)d_in[19];
    const float* bnv  = (const float*)d_in[20];
    float* out = (float*)d_out;

    const int SM1 = 15360 * (int)sizeof(float); // 61440 B
    const int SM3 = 18944 * (int)sizeof(float); // 75776 B
    cudaFuncSetAttribute(k1_mpart, cudaFuncAttributeMaxDynamicSharedMemorySize, SM1);
    cudaFuncSetAttribute(k3_main,  cudaFuncAttributeMaxDynamicSharedMemorySize, SM3);

    // k0: prep (21K elements)
    k0_prep<<<(C_ * K1P + S_ * C_ * WDP + 96 + 128 + 255) / 256, 256>>>(
        wa, ba, wb, bb, bag, bab, bam, bav, bbg, bbb, bbm, bbv,
        wd, db, bng, bnbt, bnm, bnv);

    dim3 g(NCH, N_);
    k1_mpart<<<g, 256, SM1>>>(x);

    k2_aadp<<<(N_ * S_ * 32 * ASP + 255) / 256, 256>>>(A, alph);

    k3_main<<<g, 256, SM3>>>(x, out);
}

// round 10
// speedup vs baseline: 3.6370x; 1.2751x over previous
#include <cuda_runtime.h>
#include <cstdint>

#define N_ 64
#define C_ 64
#define T_ 300
#define V_ 25
#define S_ 3
#define IC_ 16
#define OC_ 64
#define EPS_ 1e-5f
#define TV_ (T_ * V_)

#define NCH 75
#define PP 100

#define P68 68     // 272B pitch (272/16=17 odd -> ldmatrix conflict-free)
#define P36 36     // 144B pitch (144/16=9 odd)

// ---- device-global scratch ----
__device__ float g_Mpart[N_ * NCH * S_ * 625];
__device__ float g_AadpT[N_ * S_ * 25 * P36];   // [n][s][w][v] tf32, v-pads zero
__device__ float g_wabM[96 * P68];              // [r=s*32+j][c] tf32
__device__ float g_wdO[S_ * OC_ * P68];         // [s][o][c] tf32
__device__ float g_bnc[192];                    // mul[96], add[96]
__device__ float g_obnc[128];                   // sc[64], sh[64]

__device__ __forceinline__ float tanh_fast(float x) {
    float cx = fminf(fmaxf(x, -10.0f), 10.0f);
    float e = __expf(2.0f * cx);
    return __fdividef(e - 1.0f, e + 1.0f);
}
__device__ __forceinline__ float to_tf32(float x) {
    uint32_t u;
    asm("cvt.rna.tf32.f32 %0, %1;" : "=r"(u) : "f"(x));
    return __uint_as_float(u);
}
__device__ __forceinline__ void mma_tf32(float c[4],
                                         uint32_t a0, uint32_t a1, uint32_t a2, uint32_t a3,
                                         uint32_t b0, uint32_t b1) {
    asm volatile("mma.sync.aligned.m16n8k8.row.col.f32.tf32.tf32.f32 "
                 "{%0,%1,%2,%3}, {%4,%5,%6,%7}, {%8,%9}, {%0,%1,%2,%3};"
                 : "+f"(c[0]), "+f"(c[1]), "+f"(c[2]), "+f"(c[3])
                 : "r"(a0), "r"(a1), "r"(a2), "r"(a3), "r"(b0), "r"(b1));
}
__device__ __forceinline__ void ldsm_x4(uint32_t& r0, uint32_t& r1, uint32_t& r2, uint32_t& r3,
                                        uint32_t a) {
    asm volatile("ldmatrix.sync.aligned.m8n8.x4.shared.b16 {%0,%1,%2,%3}, [%4];"
                 : "=r"(r0), "=r"(r1), "=r"(r2), "=r"(r3) : "r"(a));
}
__device__ __forceinline__ void ldsm_x2(uint32_t& r0, uint32_t& r1, uint32_t a) {
    asm volatile("ldmatrix.sync.aligned.m8n8.x2.shared.b16 {%0,%1}, [%2];"
                 : "=r"(r0), "=r"(r1) : "r"(a));
}
__device__ __forceinline__ uint32_t smem_u32(const void* p) {
    return (uint32_t)__cvta_generic_to_shared(p);
}

// =====================================================================
// k0: one-time prep of weight layouts + BN constants
// =====================================================================
__global__ void k0_prep(const float* __restrict__ wa, const float* __restrict__ ba,
                        const float* __restrict__ wb, const float* __restrict__ bb,
                        const float* __restrict__ gaA, const float* __restrict__ beA,
                        const float* __restrict__ mA,  const float* __restrict__ vA,
                        const float* __restrict__ gaB, const float* __restrict__ beB,
                        const float* __restrict__ mB,  const float* __restrict__ vB,
                        const float* __restrict__ wd,  const float* __restrict__ dbias,
                        const float* __restrict__ bng, const float* __restrict__ bnb,
                        const float* __restrict__ bnm, const float* __restrict__ bnv)
{
    int gid = blockIdx.x * blockDim.x + threadIdx.x;
    if (gid < 96 * P68) {
        int r = gid / P68, c = gid % P68;
        float val = 0.0f;
        if (c < C_) {
            int s = r >> 5, j = r & 31;
            val = (j < IC_) ? wa[(s * IC_ + j) * C_ + c]
                            : wb[(s * IC_ + (j - 16)) * C_ + c];
            val = to_tf32(val);
        }
        g_wabM[gid] = val;
        return;
    }
    int g2 = gid - 96 * P68;
    if (g2 < S_ * OC_ * P68) {
        int so = g2 / P68, c = g2 % P68;
        g_wdO[g2] = (c < C_) ? to_tf32(wd[so * C_ + c]) : 0.0f;
        return;
    }
    int g3 = g2 - S_ * OC_ * P68;
    if (g3 < 96) {
        int s = g3 >> 5, j = g3 & 31;
        int i = (j < IC_) ? j : j - 16;
        int off = s * IC_ + i;
        float g, be, mm, vv, bias;
        if (j < IC_) { g = gaA[off]; be = beA[off]; mm = mA[off]; vv = vA[off]; bias = ba[off]; }
        else         { g = gaB[off]; be = beB[off]; mm = mB[off]; vv = vB[off]; bias = bb[off]; }
        float sc = g * rsqrtf(vv + EPS_);
        g_bnc[g3] = sc;
        g_bnc[96 + g3] = be + (bias - mm) * sc;
        return;
    }
    int g4 = g3 - 96;
    if (g4 < OC_) {
        float scv = bng[g4] * rsqrtf(bnv[g4] + EPS_);
        g_obnc[g4] = scv;
        g_obnc[64 + g4] = bnb[g4] + (dbias[g4] + dbias[OC_ + g4] + dbias[2 * OC_ + g4] - bnm[g4]) * scv;
    }
}

// =====================================================================
// k1: per (n, 4-t chunk):
//  stage1: [96 x 100 x 64] MMA via ldmatrix, BN+tanh on frags,
//          scatter into astM/bstM [v][k=(i,tl)]
//  stage2: per s, M[25x25] = a^T b via ldmatrix -> gmem partials
// smem 13616 floats = 54464B -> 3 CTAs/SM
// =====================================================================
__global__ __launch_bounds__(256, 3)
void k1_mpart(const float* __restrict__ x)
{
    extern __shared__ float sm1[];
    float* wabM = sm1;           // 96*68 = 6528   [r][c]
    float* xs2  = sm1 + 6528;    // 100*68 = 6800  [p][c] (+overrun pad)
    float* ab2  = sm1;           // stage2 overlay: [s][ast 25*68][bst 25*68] = 10200

    const int n = blockIdx.y, chunk = blockIdx.x, tid = threadIdx.x;
    const int lane = tid & 31, warp = tid >> 5;
    const int qk = lane & 3, qm = lane >> 2;

    // ---- stage wabM: linear f4 copy
    for (int idx = tid; idx < 6528 / 4; idx += 256)
        ((float4*)wabM)[idx] = ((const float4*)g_wabM)[idx];
    // ---- stage xs2 [p][c] via 4x4 register-tile transpose (coalesced LDG)
    const float* xbase = x + (size_t)n * (C_ * TV_) + chunk * PP;
    for (int t = tid; t < 400; t += 256) {
        int q = t % 25, c4 = t / 25;
        const float* src = xbase + (c4 * 4) * TV_ + q * 4;
        float4 r0 = *(const float4*)(src);
        float4 r1 = *(const float4*)(src + TV_);
        float4 r2 = *(const float4*)(src + 2 * TV_);
        float4 r3 = *(const float4*)(src + 3 * TV_);
        float4 o;
        o.x = r0.x; o.y = r1.x; o.z = r2.x; o.w = r3.x;
        *(float4*)(xs2 + (4 * q + 0) * P68 + c4 * 4) = o;
        o.x = r0.y; o.y = r1.y; o.z = r2.y; o.w = r3.y;
        *(float4*)(xs2 + (4 * q + 1) * P68 + c4 * 4) = o;
        o.x = r0.z; o.y = r1.z; o.z = r2.z; o.w = r3.z;
        *(float4*)(xs2 + (4 * q + 2) * P68 + c4 * 4) = o;
        o.x = r0.w; o.y = r1.w; o.z = r2.w; o.w = r3.w;
        *(float4*)(xs2 + (4 * q + 3) * P68 + c4 * 4) = o;
    }
    __syncthreads();

    // ---- stage1: warps 0..5 own m-strip mt=warp; 13 nt; K=64
    float acc[13][4];
    if (warp < 6) {
        #pragma unroll
        for (int t = 0; t < 13; ++t)
            #pragma unroll
            for (int r = 0; r < 4; ++r) acc[t][r] = 0.0f;
        const uint32_t abase = smem_u32(wabM) + (warp * 16 + (lane & 15)) * 272
                             + ((lane >> 4) << 4);
        const uint32_t bbase = smem_u32(xs2) + (lane & 7) * 272 + (((lane >> 3) & 1) << 4);
        #pragma unroll
        for (int k0 = 0; k0 < 8; ++k0) {
            uint32_t a0, a1, a2, a3;
            ldsm_x4(a0, a1, a2, a3, abase + k0 * 32);
            #pragma unroll
            for (int nt = 0; nt < 13; ++nt) {
                uint32_t b0, b1;
                ldsm_x2(b0, b1, bbase + nt * 8 * 272 + k0 * 32);
                mma_tf32(acc[nt], a0, a1, a2, a3, b0, b1);
            }
        }
    }
    __syncthreads();   // done with wabM/xs2; overlay writable

    // ---- BN + tanh, scatter to astM/bstM [v][i*4+tl]
    if (warp < 6) {
        #pragma unroll
        for (int half = 0; half < 2; ++half) {
            int r = warp * 16 + qm + half * 8;
            float mu = g_bnc[r], ad = g_bnc[96 + r];
            int s = r >> 5, j = r & 31, i = j & 15;
            float* dstb = ab2 + s * 3400 + ((j < IC_) ? 0 : 1700);
            #pragma unroll
            for (int nt = 0; nt < 13; ++nt) {
                #pragma unroll
                for (int e = 0; e < 2; ++e) {
                    int p = nt * 8 + qk * 2 + e;
                    if (p < PP) {
                        int tl = p / 25, v = p - tl * 25;
                        float val = tanh_fast(fmaf(acc[nt][half * 2 + e], mu, ad));
                        dstb[v * P68 + i * 4 + tl] = val;
                    }
                }
            }
        }
    }
    __syncthreads();

    // ---- stage2: 24 tasks (s, mtv, ntw), 3/warp, K=64, ldmatrix both sides
    float* dst = g_Mpart + (size_t)(n * NCH + chunk) * (S_ * 625);
    #pragma unroll
    for (int ti = 0; ti < 3; ++ti) {
        int task = warp * 3 + ti;
        int s = task >> 3, mtv = (task >> 2) & 1, ntw = task & 3;
        const uint32_t abase = smem_u32(ab2 + s * 3400)
                             + (mtv * 16 + (lane & 15)) * 272 + ((lane >> 4) << 4);
        const uint32_t bbase = smem_u32(ab2 + s * 3400 + 1700)
                             + (ntw * 8 + (lane & 7)) * 272 + (((lane >> 3) & 1) << 4);
        float acc2[4] = {0.0f, 0.0f, 0.0f, 0.0f};
        #pragma unroll
        for (int k0 = 0; k0 < 8; ++k0) {
            uint32_t a0, a1, a2, a3, b0, b1;
            ldsm_x4(a0, a1, a2, a3, abase + k0 * 32);
            ldsm_x2(b0, b1, bbase + k0 * 32);
            mma_tf32(acc2, a0, a1, a2, a3, b0, b1);
        }
        #pragma unroll
        for (int half = 0; half < 2; ++half) {
            int v = mtv * 16 + qm + half * 8;
            #pragma unroll
            for (int e = 0; e < 2; ++e) {
                int w = ntw * 8 + qk * 2 + e;
                if (v < V_ && w < V_)
                    dst[s * 625 + v * 25 + w] = acc2[half * 2 + e];
            }
        }
    }
}

// =====================================================================
// k2: reduce partial M -> g_AadpT [n][s][w][v] tf32 (transposed, padded)
// =====================================================================
__global__ void k2_aadp(const float* __restrict__ A, const float* __restrict__ alpha)
{
    int gid = blockIdx.x * blockDim.x + threadIdx.x;
    if (gid >= N_ * S_ * 25 * P36) return;
    int n = gid / (S_ * 25 * P36);
    int rem = gid % (S_ * 25 * P36);
    int s = rem / (25 * P36);
    int r = rem % (25 * P36);
    int w = r / P36, v = r % P36;
    float val = 0.0f;
    if (v < V_) {
        const float* src = g_Mpart + (size_t)n * NCH * (S_ * 625) + s * 625 + v * 25 + w;
        float sum = 0.0f;
        #pragma unroll 5
        for (int ch = 0; ch < NCH; ++ch) sum += src[(size_t)ch * (S_ * 625)];
        val = to_tf32(A[s * 625 + v * 25 + w] + tanh_fast(sum * (1.0f / 4800.0f)) * alpha[0]);
    }
    g_AadpT[gid] = val;
}

// =====================================================================
// k3: per (n, 4-t chunk):
//  phase1: U[(c,tl)][w] = xsA[m][k=v] x as3T (m=256,n=32,k=32) -> us2 [p][c]
//  phase2: Y[o][p] += wdO (gmem A) x us2 (m=64,n=104,k=64)
//  epilogue: BN + residual + relu
// smem 18716 floats = 74864B -> 3 CTAs/SM
// =====================================================================
__global__ __launch_bounds__(256, 3)
void k3_main(const float* __restrict__ x, float* __restrict__ out)
{
    extern __shared__ float sm3[];
    float* as3T = sm3;           // 3*25*36 = 2700 [s][w][v] (+overrun into us2)
    float* us2  = sm3 + 2700;    // 100*68 = 6800 [p][c] (+overrun into xsA)
    float* xsA  = sm3 + 9500;    // 256*36 = 9216 [(c,tl)][v]

    const int n = blockIdx.y, chunk = blockIdx.x, tid = threadIdx.x;
    const int lane = tid & 31, warp = tid >> 5;
    const int qk = lane & 3, qm = lane >> 2;

    const float* xbase = x + (size_t)n * (C_ * TV_) + chunk * PP;

    // ---- stage xsA: coalesced f4 LDG, scalar STS into [m=(c,tl)][v]
    for (int idx4 = tid; idx4 < 64 * 25; idx4 += 256) {
        int c = idx4 / 25, q = idx4 % 25;
        float4 r = *(const float4*)(xbase + c * TV_ + q * 4);
        #pragma unroll
        for (int j = 0; j < 4; ++j) {
            int p = 4 * q + j;
            int tl = p / 25, v = p - tl * 25;
            float val = (j == 0) ? r.x : (j == 1) ? r.y : (j == 2) ? r.z : r.w;
            xsA[(c * 4 + tl) * P36 + v] = val;
        }
    }
    // zero xsA k-pad cols 25..31 (they multiply as3T's zero rows; avoid NaN*0)
    for (int idx = tid; idx < 256 * 7; idx += 256) {
        int row = idx / 7, cc = 25 + idx % 7;
        xsA[row * P36 + cc] = 0.0f;
    }
    // ---- stage as3T: linear f4 copy
    {
        const float4* src = (const float4*)(g_AadpT + (size_t)n * (S_ * 25 * P36));
        for (int idx = tid; idx < (S_ * 25 * P36) / 4; idx += 256)
            ((float4*)as3T)[idx] = src[idx];
    }
    __syncthreads();

    const int mtY = warp >> 1;
    const int ntb = (warp & 1) ? 7 : 0;
    const int nnt = (warp & 1) ? 6 : 7;
    float accY[7][4];
    #pragma unroll
    for (int t = 0; t < 7; ++t)
        #pragma unroll
        for (int r = 0; r < 4; ++r) accY[t][r] = 0.0f;

    const uint32_t aoff = (lane & 15) * 144 + ((lane >> 4) << 4);
    const uint32_t boff36 = (lane & 7) * 144 + (((lane >> 3) & 1) << 4);
    const uint32_t boff68 = (lane & 7) * 272 + (((lane >> 3) & 1) << 4);

    for (int s = 0; s < S_; ++s) {
        // ---- phase1: warp owns m-tiles {warp, warp+8}; 4 nt; K=32
        {
            float acc1[2][4][4];
            #pragma unroll
            for (int m2 = 0; m2 < 2; ++m2)
                #pragma unroll
                for (int t = 0; t < 4; ++t)
                    #pragma unroll
                    for (int r = 0; r < 4; ++r) acc1[m2][t][r] = 0.0f;
            const uint32_t ab0 = smem_u32(xsA) + warp * 16 * 144 + aoff;
            const uint32_t ab1 = ab0 + 8 * 16 * 144;
            const uint32_t bb = smem_u32(as3T) + s * 900 * 4 + boff36;
            #pragma unroll
            for (int k0 = 0; k0 < 4; ++k0) {
                uint32_t a[2][4];
                ldsm_x4(a[0][0], a[0][1], a[0][2], a[0][3], ab0 + k0 * 32);
                ldsm_x4(a[1][0], a[1][1], a[1][2], a[1][3], ab1 + k0 * 32);
                #pragma unroll
                for (int nt = 0; nt < 4; ++nt) {
                    uint32_t b0, b1;
                    ldsm_x2(b0, b1, bb + nt * 8 * 144 + k0 * 32);
                    mma_tf32(acc1[0][nt], a[0][0], a[0][1], a[0][2], a[0][3], b0, b1);
                    mma_tf32(acc1[1][nt], a[1][0], a[1][1], a[1][2], a[1][3], b0, b1);
                }
            }
            // scatter U -> us2[p][c]
            #pragma unroll
            for (int m2 = 0; m2 < 2; ++m2) {
                #pragma unroll
                for (int half = 0; half < 2; ++half) {
                    int m = (warp + m2 * 8) * 16 + qm + half * 8;
                    int c = m >> 2, tl = m & 3;
                    #pragma unroll
                    for (int nt = 0; nt < 4; ++nt) {
                        #pragma unroll
                        for (int e = 0; e < 2; ++e) {
                            int w = nt * 8 + qk * 2 + e;
                            if (w < V_)
                                us2[(tl * 25 + w) * P68 + c] = acc1[m2][nt][half * 2 + e];
                        }
                    }
                }
            }
        }
        __syncthreads();

        // ---- phase2: A scalar LDG from g_wdO (L1-hot), B x2-ldmatrix from us2
        const float* wdb = g_wdO + s * (OC_ * P68) + (mtY * 16 + qm) * P68 + qk;
        const uint32_t ub = smem_u32(us2) + boff68;
        #pragma unroll
        for (int k0 = 0; k0 < 8; ++k0) {
            int kk = k0 * 8;
            uint32_t a0 = __float_as_uint(wdb[kk]);
            uint32_t a1 = __float_as_uint(wdb[8 * P68 + kk]);
            uint32_t a2 = __float_as_uint(wdb[kk + 4]);
            uint32_t a3 = __float_as_uint(wdb[8 * P68 + kk + 4]);
            #pragma unroll
            for (int j = 0; j < 7; ++j) {
                if (j < nnt) {
                    int nt = ntb + j;
                    uint32_t b0, b1;
                    ldsm_x2(b0, b1, ub + nt * 8 * 272 + k0 * 32);
                    mma_tf32(accY[j], a0, a1, a2, a3, b0, b1);
                }
            }
        }
        __syncthreads();   // us2 consumed; next s may overwrite
    }

    // ---- epilogue: BN + residual + relu
    float* obase = out + (size_t)n * (C_ * TV_) + chunk * PP;
    #pragma unroll
    for (int half = 0; half < 2; ++half) {
        int o = mtY * 16 + qm + half * 8;
        float sc = g_obnc[o], sh = g_obnc[64 + o];
        const float* xr = xbase + o * TV_;
        float* orow = obase + o * TV_;
        #pragma unroll
        for (int j = 0; j < 7; ++j) {
            if (j < nnt) {
                int nt = ntb + j;
                #pragma unroll
                for (int e = 0; e < 2; ++e) {
                    int p = nt * 8 + qk * 2 + e;
                    if (p < PP) {
                        float val = fmaf(accY[j][half * 2 + e], sc, sh) + xr[p];
                        orow[p] = fmaxf(val, 0.0f);
                    }
                }
            }
        }
    }
}

// =====================================================================
extern "C" void kernel_launch(void* const* d_in, const int* in_sizes, int n_in,
                              void* d_out, int out_size)
{
    const float* x    = (const float*)d_in[0];
    const float* A    = (const float*)d_in[1];
    const float* alph = (const float*)d_in[2];
    const float* wa   = (const float*)d_in[3];
    const float* ba   = (const float*)d_in[4];
    const float* wb   = (const float*)d_in[5];
    const float* bb   = (const float*)d_in[6];
    const float* bag  = (const float*)d_in[7];
    const float* bab  = (const float*)d_in[8];
    const float* bam  = (const float*)d_in[9];
    const float* bav  = (const float*)d_in[10];
    const float* bbg  = (const float*)d_in[11];
    const float* bbb  = (const float*)d_in[12];
    const float* bbm  = (const float*)d_in[13];
    const float* bbv  = (const float*)d_in[14];
    const float* wd   = (const float*)d_in[15];
    const float* db   = (const float*)d_in[16];
    const float* bng  = (const float*)d_in[17];
    const float* bnbt = (const float*)d_in[18];
    const float* bnm  = (const float*)d_in[19];
    const float* bnv  = (const float*)d_in[20];
    float* out = (float*)d_out;

    const int SM1 = 13616 * (int)sizeof(float); // 54464 B -> 3 CTAs
    const int SM3 = 18716 * (int)sizeof(float); // 74864 B -> 3 CTAs
    cudaFuncSetAttribute(k1_mpart, cudaFuncAttributeMaxDynamicSharedMemorySize, SM1);
    cudaFuncSetAttribute(k3_main,  cudaFuncAttributeMaxDynamicSharedMemorySize, SM3);

    int prep_elems = 96 * P68 + S_ * OC_ * P68 + 96 + OC_;
    k0_prep<<<(prep_elems + 255) / 256, 256>>>(
        wa, ba, wb, bb, bag, bab, bam, bav, bbg, bbb, bbm, bbv,
        wd, db, bng, bnbt, bnm, bnv);

    dim3 g(NCH, N_);
    k1_mpart<<<g, 256, SM1>>>(x);

    k2_aadp<<<(N_ * S_ * 25 * P36 + 255) / 256, 256>>>(A, alph);

    k3_main<<<g, 256, SM3>>>(x, out);
}